// round 5
// baseline (speedup 1.0000x reference)
#include <cuda_runtime.h>
#include <cuda_bf16.h>
#include <math.h>

#define NPTS 16384
#define KNB  16
#define ASTR 40   // smem row stride (bf16 elems): 32 + 8 pad, conflict-free, 80B (16B-aligned)

// ---------------- device scratch (static: no allocations allowed) ----------------
__device__ float d_geo[NPTS * 4];
__device__ int   d_knn32[NPTS * KNB];
__device__ int   d_knn_bad;                  // 0 => int64 knn, nonzero => int32
__device__ float d_G1[NPTS * 128];
__device__ float d_C0[(size_t)NPTS * 512];
__device__ float d_fa[(size_t)NPTS * 512];
__device__ float d_fb[(size_t)NPTS * 512];
__device__ float d_xr[(size_t)NPTS * 640];   // [x1 (128) | f @ w_res^T (512)]
__device__ float d_ax1[NPTS * 128];
__device__ float d_dv[512];
__device__ float d_bsum[512];

// bf16 hi/lo planes (GEMM operands)
__device__ __nv_bfloat16 d_Gch[(size_t)NPTS * 384], d_Gcl[(size_t)NPTS * 384];
__device__ __nv_bfloat16 d_fah[(size_t)NPTS * 512], d_fal[(size_t)NPTS * 512];
__device__ __nv_bfloat16 d_fbh[(size_t)NPTS * 512], d_fbl[(size_t)NPTS * 512];
__device__ __nv_bfloat16 d_aaxh[NPTS * 128],        d_aaxl[NPTS * 128];
__device__ __nv_bfloat16 d_w2h[512 * 512],          d_w2l[512 * 512];
__device__ __nv_bfloat16 d_wch[640 * 512],          d_wcl[640 * 512]; // [w_mlp1;w_res]

__device__ __forceinline__ void cvt_hl(float x, __nv_bfloat16& h, __nv_bfloat16& l) {
    h = __float2bfloat16(x);
    l = __float2bfloat16(x - __bfloat162float(h));
}

// ---------------- knn dtype detection + convert ----------------
__global__ void k_detect(const void* __restrict__ knn) {
    const long long* p = (const long long*)knn;
    const int total = NPTS * KNB / 2;
    int local = 0;
    for (int i = blockIdx.x * blockDim.x + threadIdx.x; i < total; i += gridDim.x * blockDim.x) {
        long long v = p[i];
        if (v < 0 || v >= NPTS) local = 1;
    }
    if (local) atomicOr(&d_knn_bad, 1);
}

__global__ void k_cvt(const void* __restrict__ knn) {
    int i = blockIdx.x * blockDim.x + threadIdx.x;
    if (i >= NPTS * KNB) return;
    if (d_knn_bad)
        d_knn32[i] = ((const int*)knn)[i];
    else
        d_knn32[i] = (int)((const long long*)knn)[i];
}

// ---------------- weight hi/lo planes (once per launch) ----------------
__global__ void k_wcvt(const float* __restrict__ w_mlp2, const float* __restrict__ w_mlp1,
                       const float* __restrict__ w_res) {
    int i = blockIdx.x * blockDim.x + threadIdx.x;
    if (i >= 640 * 512) return;
    __nv_bfloat16 h, l;
    if (i < 512 * 512) {
        cvt_hl(w_mlp2[i], h, l);
        d_w2h[i] = h; d_w2l[i] = l;
    }
    float v = (i < 128 * 512) ? w_mlp1[i] : w_res[i - 128 * 512];
    cvt_hl(v, h, l);
    d_wch[i] = h; d_wcl[i] = l;
}

// ---------------- prep: geo mean ----------------
__global__ void k_prep(const float* __restrict__ inp) {
    int n = blockIdx.x * blockDim.x + threadIdx.x;
    if (n >= NPTS) return;
    float xi = inp[3 * n + 0], yi = inp[3 * n + 1], zi = inp[3 * n + 2];
    float sx = 0.f, sy = 0.f, sz = 0.f, sn = 0.f;
#pragma unroll
    for (int k = 0; k < KNB; k++) {
        int j = d_knn32[n * KNB + k];
        float dx = xi - inp[3 * j + 0];
        float dy = yi - inp[3 * j + 1];
        float dz = zi - inp[3 * j + 2];
        sx += dx; sy += dy; sz += dz;
        sn += sqrtf(dx * dx + dy * dy + dz * dz);
    }
    const float s = 1.0f / KNB;
    d_geo[n * 4 + 0] = sx * s;
    d_geo[n * 4 + 1] = sy * s;
    d_geo[n * 4 + 2] = sz * s;
    d_geo[n * 4 + 3] = sn * s;
}

// ---------------- tiny geo linears (persistent: 256 blocks x 64 pts) + vec tail ----------------
__global__ void __launch_bounds__(256) k_smallg(
        const float* __restrict__ w_lfa1, const float* __restrict__ b_lfa1,
        const float* __restrict__ w_lfa2, const float* __restrict__ b_lfa2,
        const float* __restrict__ w_mlp2, const float* __restrict__ b_mlp1,
        const float* __restrict__ b_mlp2, const float* __restrict__ b_res) {
    int tid = threadIdx.x;
    if (blockIdx.x == 256) {             // vector precompute tail block
        int j = tid * 2;
        if (j < 512) {
#pragma unroll
            for (int t = 0; t < 2; t++) {
                int jj = j + t;
                d_bsum[jj] = b_mlp2[jj] + b_res[jj];
                float s = 0.f;
#pragma unroll 8
                for (int c = 0; c < 128; c++) s += w_mlp2[jj * 512 + 384 + c] * b_mlp1[c];
                d_dv[jj] = s;
            }
        }
        return;
    }
    __shared__ float s_w2[256 * 4], s_b2[256], s_w1[128 * 4], s_b1[128];
    for (int i = tid; i < 1024; i += 256) s_w2[i] = w_lfa2[i];
    for (int i = tid; i < 512;  i += 256) s_w1[i] = w_lfa1[i];
    for (int i = tid; i < 256;  i += 256) s_b2[i] = b_lfa2[i];
    if (tid < 128) s_b1[tid] = b_lfa1[tid];
    __syncthreads();
    int wid = tid >> 5, lane = tid & 31;
#pragma unroll 1
    for (int p = 0; p < 8; p++) {
        int n = (blockIdx.x * 8 + wid) * 8 + p;
        float4 g = *(const float4*)(d_geo + n * 4);
#pragma unroll
        for (int t = 0; t < 2; t++) {
            int j0 = t * 128 + lane * 4;
            float r[4];
#pragma unroll
            for (int u = 0; u < 4; u++) {
                int j = j0 + u;
                r[u] = s_b2[j] + g.x * s_w2[j * 4 + 0] + g.y * s_w2[j * 4 + 1]
                               + g.z * s_w2[j * 4 + 2] + g.w * s_w2[j * 4 + 3];
            }
            __nv_bfloat16 h[4], l[4];
#pragma unroll
            for (int u = 0; u < 4; u++) cvt_hl(r[u], h[u], l[u]);
            size_t o = (size_t)n * 384 + j0;
            *(__nv_bfloat162*)(d_Gch + o)     = __nv_bfloat162(h[0], h[1]);
            *(__nv_bfloat162*)(d_Gch + o + 2) = __nv_bfloat162(h[2], h[3]);
            *(__nv_bfloat162*)(d_Gcl + o)     = __nv_bfloat162(l[0], l[1]);
            *(__nv_bfloat162*)(d_Gcl + o + 2) = __nv_bfloat162(l[2], l[3]);
        }
        {
            int j0 = lane * 4;
            float r[4];
#pragma unroll
            for (int u = 0; u < 4; u++) {
                int j = j0 + u;
                r[u] = s_b1[j] + g.x * s_w1[j * 4 + 0] + g.y * s_w1[j * 4 + 1]
                               + g.z * s_w1[j * 4 + 2] + g.w * s_w1[j * 4 + 3];
            }
            *(float4*)(d_G1 + (size_t)n * 128 + j0) = make_float4(r[0], r[1], r[2], r[3]);
        }
    }
}

// ---------------- gather-mean kernels (one warp per point) ----------------
// mode0: d_G1 fp32 -> Gcat planes cols 256:384
__global__ void __launch_bounds__(256) k_gather0() {
    int t = blockIdx.x * blockDim.x + threadIdx.x;
    int n = t >> 5; if (n >= NPTS) return;
    int lane = t & 31;
    const int* kn = d_knn32 + n * KNB;
    float a[4] = {};
#pragma unroll
    for (int k = 0; k < KNB; k++) {
        float4 v = *(const float4*)(d_G1 + (size_t)kn[k] * 128 + lane * 4);
        a[0] += v.x; a[1] += v.y; a[2] += v.z; a[3] += v.w;
    }
    const float s = 1.0f / KNB;
    __nv_bfloat16 h[4], l[4];
#pragma unroll
    for (int u = 0; u < 4; u++) cvt_hl(a[u] * s, h[u], l[u]);
    size_t o = (size_t)n * 384 + 256 + lane * 4;
    *(__nv_bfloat162*)(d_Gch + o)     = __nv_bfloat162(h[0], h[1]);
    *(__nv_bfloat162*)(d_Gch + o + 2) = __nv_bfloat162(h[2], h[3]);
    *(__nv_bfloat162*)(d_Gcl + o)     = __nv_bfloat162(l[0], l[1]);
    *(__nv_bfloat162*)(d_Gcl + o + 2) = __nv_bfloat162(l[2], l[3]);
}

// mode1: d_xr (x1 part, ld 640) -> d_ax1 fp32
__global__ void __launch_bounds__(256) k_gather1() {
    int t = blockIdx.x * blockDim.x + threadIdx.x;
    int n = t >> 5; if (n >= NPTS) return;
    int lane = t & 31;
    const int* kn = d_knn32 + n * KNB;
    float a[4] = {};
#pragma unroll
    for (int k = 0; k < KNB; k++) {
        float4 v = *(const float4*)(d_xr + (size_t)kn[k] * 640 + lane * 4);
        a[0] += v.x; a[1] += v.y; a[2] += v.z; a[3] += v.w;
    }
    const float s = 1.0f / KNB;
    *(float4*)(d_ax1 + (size_t)n * 128 + lane * 4) =
        make_float4(a[0] * s, a[1] * s, a[2] * s, a[3] * s);
}

// mode2: d_ax1 fp32 -> aax planes
__global__ void __launch_bounds__(256) k_gather2() {
    int t = blockIdx.x * blockDim.x + threadIdx.x;
    int n = t >> 5; if (n >= NPTS) return;
    int lane = t & 31;
    const int* kn = d_knn32 + n * KNB;
    float a[4] = {};
#pragma unroll
    for (int k = 0; k < KNB; k++) {
        float4 v = *(const float4*)(d_ax1 + (size_t)kn[k] * 128 + lane * 4);
        a[0] += v.x; a[1] += v.y; a[2] += v.z; a[3] += v.w;
    }
    const float s = 1.0f / KNB;
    __nv_bfloat16 h[4], l[4];
#pragma unroll
    for (int u = 0; u < 4; u++) cvt_hl(a[u] * s, h[u], l[u]);
    size_t o = (size_t)n * 128 + lane * 4;
    *(__nv_bfloat162*)(d_aaxh + o)     = __nv_bfloat162(h[0], h[1]);
    *(__nv_bfloat162*)(d_aaxh + o + 2) = __nv_bfloat162(h[2], h[3]);
    *(__nv_bfloat162*)(d_aaxl + o)     = __nv_bfloat162(l[0], l[1]);
    *(__nv_bfloat162*)(d_aaxl + o + 2) = __nv_bfloat162(l[2], l[3]);
}

// ================= bf16x3 tensor-core GEMM core (plane inputs, cp.async 2-stage) =================
__device__ __forceinline__ void mma16816(float* c, const unsigned* a, unsigned b0, unsigned b1) {
    asm volatile(
        "mma.sync.aligned.m16n8k16.row.col.f32.bf16.bf16.f32 "
        "{%0,%1,%2,%3}, {%4,%5,%6,%7}, {%8,%9}, {%0,%1,%2,%3};"
        : "+f"(c[0]), "+f"(c[1]), "+f"(c[2]), "+f"(c[3])
        : "r"(a[0]), "r"(a[1]), "r"(a[2]), "r"(a[3]), "r"(b0), "r"(b1));
}

__device__ __forceinline__ void cp16(__nv_bfloat16* s, const __nv_bfloat16* g) {
    unsigned sa = (unsigned)__cvta_generic_to_shared(s);
    asm volatile("cp.async.cg.shared.global [%0], [%1], 16;" :: "r"(sa), "l"(g));
}

#define PLANE (128 * ASTR)
#define GEMM_SMEM (2 * 4 * PLANE * 2)   // bytes: 2 stages x 4 planes x 128*ASTR bf16

__device__ __forceinline__ void ld_stage(__nv_bfloat16* s,
        const __nv_bfloat16* Ah, const __nv_bfloat16* Al, int lda,
        const __nv_bfloat16* Bh, const __nv_bfloat16* Bl, int ldb,
        int k0, int tid) {
#pragma unroll
    for (int i = 0; i < 2; i++) {
        int chunk = tid + i * 256;
        int r = chunk >> 2, c8 = (chunk & 3) * 8;
        cp16(s + 0 * PLANE + r * ASTR + c8, Ah + (size_t)r * lda + k0 + c8);
        cp16(s + 1 * PLANE + r * ASTR + c8, Al + (size_t)r * lda + k0 + c8);
        cp16(s + 2 * PLANE + r * ASTR + c8, Bh + (size_t)r * ldb + k0 + c8);
        cp16(s + 3 * PLANE + r * ASTR + c8, Bl + (size_t)r * ldb + k0 + c8);
    }
}

__device__ __forceinline__ void gemm_mma(
        const __nv_bfloat16* __restrict__ Ah, const __nv_bfloat16* __restrict__ Al, int lda,
        const __nv_bfloat16* __restrict__ Bh, const __nv_bfloat16* __restrict__ Bl, int ldb,
        int K, float (&acc)[2][8][4]) {
    extern __shared__ __nv_bfloat16 smdyn[];
    const int tid = threadIdx.x;
    const int lane = tid & 31, wid = tid >> 5;
    const int warp_m = wid & 3, warp_n = wid >> 2;
    const int grp = lane >> 2, tig = lane & 3;
    const int nk = K / 32;

    ld_stage(smdyn, Ah, Al, lda, Bh, Bl, ldb, 0, tid);
    asm volatile("cp.async.commit_group;");
    for (int t = 0; t < nk; t++) {
        int st = t & 1;
        if (t + 1 < nk) {
            ld_stage(smdyn + (st ^ 1) * 4 * PLANE, Ah, Al, lda, Bh, Bl, ldb, (t + 1) * 32, tid);
            asm volatile("cp.async.commit_group;");
            asm volatile("cp.async.wait_group 1;");
        } else {
            asm volatile("cp.async.wait_group 0;");
        }
        __syncthreads();
        const __nv_bfloat16* sAh = smdyn + st * 4 * PLANE;
        const __nv_bfloat16* sAl = sAh + PLANE;
        const __nv_bfloat16* sBh = sAh + 2 * PLANE;
        const __nv_bfloat16* sBl = sAh + 3 * PLANE;
#pragma unroll
        for (int ks = 0; ks < 32; ks += 16) {
            unsigned ah[2][4], al[2][4];
#pragma unroll
            for (int mi = 0; mi < 2; mi++) {
                int r = warp_m * 32 + mi * 16 + grp;
                const __nv_bfloat16* ph = sAh + r * ASTR + ks + 2 * tig;
                const __nv_bfloat16* pl = sAl + r * ASTR + ks + 2 * tig;
                ah[mi][0] = *(const unsigned*)(ph);
                ah[mi][1] = *(const unsigned*)(ph + 8 * ASTR);
                ah[mi][2] = *(const unsigned*)(ph + 8);
                ah[mi][3] = *(const unsigned*)(ph + 8 * ASTR + 8);
                al[mi][0] = *(const unsigned*)(pl);
                al[mi][1] = *(const unsigned*)(pl + 8 * ASTR);
                al[mi][2] = *(const unsigned*)(pl + 8);
                al[mi][3] = *(const unsigned*)(pl + 8 * ASTR + 8);
            }
#pragma unroll
            for (int ni = 0; ni < 8; ni++) {
                int r = warp_n * 64 + ni * 8 + grp;
                const __nv_bfloat16* ph = sBh + r * ASTR + ks + 2 * tig;
                const __nv_bfloat16* pl = sBl + r * ASTR + ks + 2 * tig;
                unsigned bh0 = *(const unsigned*)(ph);
                unsigned bh1 = *(const unsigned*)(ph + 8);
                unsigned bl0 = *(const unsigned*)(pl);
                unsigned bl1 = *(const unsigned*)(pl + 8);
#pragma unroll
                for (int mi = 0; mi < 2; mi++) {
                    mma16816(acc[mi][ni], ah[mi], bh0, bh1);
                    mma16816(acc[mi][ni], ah[mi], bl0, bl1);
                    mma16816(acc[mi][ni], al[mi], bh0, bh1);
                }
            }
        }
        __syncthreads();
    }
}

#define EPILOG_COORDS() \
    const int lane = threadIdx.x & 31, wid = threadIdx.x >> 5; \
    const int warp_m = wid & 3, warp_n = wid >> 2; \
    const int grp = lane >> 2, tig = lane & 3;

// ---------------- GEMM C0: Gcat @ W2[:, :384]^T + bsum ; fa = C0 + dv (+ hl planes) ----------------
__global__ void __launch_bounds__(256, 2) k_gemmC0() {
    float acc[2][8][4] = {};
    gemm_mma(d_Gch + (size_t)blockIdx.x * 128 * 384, d_Gcl + (size_t)blockIdx.x * 128 * 384, 384,
             d_w2h + (size_t)blockIdx.y * 128 * 512, d_w2l + (size_t)blockIdx.y * 128 * 512, 512,
             384, acc);
    EPILOG_COORDS();
#pragma unroll
    for (int mi = 0; mi < 2; mi++) {
#pragma unroll
        for (int ni = 0; ni < 8; ni++) {
            int r0 = blockIdx.x * 128 + warp_m * 32 + mi * 16 + grp;
            int cc = blockIdx.y * 128 + warp_n * 64 + ni * 8 + tig * 2;
            float2 bs = *(const float2*)(d_bsum + cc);
            float2 dv = *(const float2*)(d_dv + cc);
            float* a = acc[mi][ni];
#pragma unroll
            for (int h2 = 0; h2 < 2; h2++) {
                int r = r0 + h2 * 8;
                size_t o = (size_t)r * 512 + cc;
                float c0 = a[2 * h2 + 0] + bs.x, c1 = a[2 * h2 + 1] + bs.y;
                *(float2*)(d_C0 + o) = make_float2(c0, c1);
                float f0 = c0 + dv.x, f1 = c1 + dv.y;
                *(float2*)(d_fa + o) = make_float2(f0, f1);
                __nv_bfloat16 h0, l0, h1, l1;
                cvt_hl(f0, h0, l0); cvt_hl(f1, h1, l1);
                *(__nv_bfloat162*)(d_fah + o) = __nv_bfloat162(h0, h1);
                *(__nv_bfloat162*)(d_fal + o) = __nv_bfloat162(l0, l1);
            }
        }
    }
}

// ---------------- GEMM1: xr = f @ [w_mlp1 ; w_res]^T  (N=640, K=512) ----------------
__global__ void __launch_bounds__(256, 2) k_gemm1(int fsel, const float* __restrict__ b_mlp1) {
    const __nv_bfloat16* Ah = fsel ? d_fbh : d_fah;
    const __nv_bfloat16* Al = fsel ? d_fbl : d_fal;
    float acc[2][8][4] = {};
    gemm_mma(Ah + (size_t)blockIdx.x * 128 * 512, Al + (size_t)blockIdx.x * 128 * 512, 512,
             d_wch + (size_t)blockIdx.y * 128 * 512, d_wcl + (size_t)blockIdx.y * 128 * 512, 512,
             512, acc);
    EPILOG_COORDS();
#pragma unroll
    for (int mi = 0; mi < 2; mi++) {
#pragma unroll
        for (int ni = 0; ni < 8; ni++) {
            int r0 = blockIdx.x * 128 + warp_m * 32 + mi * 16 + grp;
            int cc = blockIdx.y * 128 + warp_n * 64 + ni * 8 + tig * 2;
            float2 bs = make_float2(0.f, 0.f);
            if (blockIdx.y == 0) bs = *(const float2*)(b_mlp1 + (cc & 127));
            float* a = acc[mi][ni];
            *(float2*)(d_xr + (size_t)r0 * 640 + cc)       = make_float2(a[0] + bs.x, a[1] + bs.y);
            *(float2*)(d_xr + (size_t)(r0 + 8) * 640 + cc) = make_float2(a[2] + bs.x, a[3] + bs.y);
        }
    }
}

// ---------------- GEMM2: f_new = C0 + f + r + aax1 @ W2[:,384:512]^T  (K=128) ----------------
__global__ void __launch_bounds__(256, 2) k_gemm2(int fsel, int dsel, float* __restrict__ outp) {
    const float* f = fsel ? d_fb : d_fa;
    float* dst = (dsel == 0) ? d_fb : (dsel == 1) ? d_fa : outp;
    __nv_bfloat16* dsth = (dsel == 0) ? d_fbh : d_fah;
    __nv_bfloat16* dstl = (dsel == 0) ? d_fbl : d_fal;
    float acc[2][8][4] = {};
    gemm_mma(d_aaxh + (size_t)blockIdx.x * 128 * 128, d_aaxl + (size_t)blockIdx.x * 128 * 128, 128,
             d_w2h + (size_t)blockIdx.y * 128 * 512 + 384, d_w2l + (size_t)blockIdx.y * 128 * 512 + 384, 512,
             128, acc);
    EPILOG_COORDS();
#pragma unroll
    for (int mi = 0; mi < 2; mi++) {
#pragma unroll
        for (int ni = 0; ni < 8; ni++) {
            int r0 = blockIdx.x * 128 + warp_m * 32 + mi * 16 + grp;
            int cc = blockIdx.y * 128 + warp_n * 64 + ni * 8 + tig * 2;
            float* a = acc[mi][ni];
#pragma unroll
            for (int h2 = 0; h2 < 2; h2++) {
                int r = r0 + h2 * 8;
                size_t o = (size_t)r * 512 + cc;
                float2 c0 = *(const float2*)(d_C0 + o);
                float2 fv = *(const float2*)(f + o);
                float2 rv = *(const float2*)(d_xr + (size_t)r * 640 + 128 + cc);
                float v0 = a[2 * h2 + 0] + c0.x + fv.x + rv.x;
                float v1 = a[2 * h2 + 1] + c0.y + fv.y + rv.y;
                *(float2*)(dst + o) = make_float2(v0, v1);
                if (dsel != 2) {
                    __nv_bfloat16 h0, l0, h1, l1;
                    cvt_hl(v0, h0, l0); cvt_hl(v1, h1, l1);
                    *(__nv_bfloat162*)(dsth + o) = __nv_bfloat162(h0, h1);
                    *(__nv_bfloat162*)(dstl + o) = __nv_bfloat162(l0, l1);
                }
            }
        }
    }
}

// ---------------- launch ----------------
extern "C" void kernel_launch(void* const* d_in, const int* in_sizes, int n_in,
                              void* d_out, int out_size) {
    const float* inputs = (const float*)d_in[0];
    const void*  knn    = d_in[1];
    const float* w_mlp1 = (const float*)d_in[2];
    const float* b_mlp1 = (const float*)d_in[3];
    const float* w_lfa1 = (const float*)d_in[4];
    const float* b_lfa1 = (const float*)d_in[5];
    const float* w_lfa2 = (const float*)d_in[6];
    const float* b_lfa2 = (const float*)d_in[7];
    const float* w_mlp2 = (const float*)d_in[8];
    const float* b_mlp2 = (const float*)d_in[9];
    const float* w_res  = (const float*)d_in[10];
    const float* b_res  = (const float*)d_in[11];
    float* out = (float*)d_out;

    static int smem_set = 0;
    if (!smem_set) {
        cudaFuncSetAttribute(k_gemmC0, cudaFuncAttributeMaxDynamicSharedMemorySize, GEMM_SMEM);
        cudaFuncSetAttribute(k_gemm1,  cudaFuncAttributeMaxDynamicSharedMemorySize, GEMM_SMEM);
        cudaFuncSetAttribute(k_gemm2,  cudaFuncAttributeMaxDynamicSharedMemorySize, GEMM_SMEM);
        smem_set = 1;
    }

    k_detect<<<128, 256>>>(knn);
    k_cvt<<<(NPTS * KNB) / 256, 256>>>(knn);
    k_wcvt<<<(640 * 512) / 256, 256>>>(w_mlp2, w_mlp1, w_res);
    k_prep<<<NPTS / 256, 256>>>(inputs);
    k_smallg<<<257, 256>>>(w_lfa1, b_lfa1, w_lfa2, b_lfa2,
                           w_mlp2, b_mlp1, b_mlp2, b_res);
    k_gather0<<<(NPTS * 32) / 256, 256>>>();
    dim3 gC0(128, 4);
    k_gemmC0<<<gC0, 256, GEMM_SMEM>>>();

    int fsel = 0;
    for (int it = 0; it < 3; it++) {
        dim3 g1(128, 5);
        k_gemm1<<<g1, 256, GEMM_SMEM>>>(fsel, b_mlp1);
        k_gather1<<<(NPTS * 32) / 256, 256>>>();
        k_gather2<<<(NPTS * 32) / 256, 256>>>();
        dim3 g2(128, 4);
        int dsel = (it == 2) ? 2 : (fsel == 0 ? 0 : 1);
        k_gemm2<<<g2, 256, GEMM_SMEM>>>(fsel, dsel, out);
        fsel ^= 1;
    }
    (void)in_sizes; (void)n_in; (void)out_size;
}

// round 8
// speedup vs baseline: 1.2905x; 1.2905x over previous
#include <cuda_runtime.h>
#include <cuda_fp16.h>
#include <math.h>
#include <stdint.h>

#define NPTS 16384
#define KNB  16
#define ASTR 40   // smem row stride (halfs): 32 + 8 pad, conflict-free, 80B (16B aligned)

// ---------------- device scratch (static: no allocations allowed) ----------------
__device__ float d_geo[NPTS * 4];
__device__ int   d_knn32[NPTS * KNB];
__device__ int   d_knn_bad;                  // 0 => int64 knn, nonzero => int32
__device__ float d_G1[NPTS * 128];
__device__ float d_C0[(size_t)NPTS * 512];
__device__ float d_fa[(size_t)NPTS * 512];
__device__ float d_fb[(size_t)NPTS * 512];
__device__ float d_xr[(size_t)NPTS * 640];   // [x1 (128) | f @ w_res^T (512)]
__device__ float d_ax1[NPTS * 128];
__device__ float d_dv[512];
__device__ float d_bsum[512];

// fp16 operand planes: activations single plane, weights hi/lo split
__device__ __half d_Gcf[(size_t)NPTS * 384];
__device__ __half d_faf[(size_t)NPTS * 512];
__device__ __half d_fbf[(size_t)NPTS * 512];
__device__ __half d_aaxf[NPTS * 128];
__device__ __half d_w2h[512 * 512], d_w2l[512 * 512];
__device__ __half d_wch[640 * 512], d_wcl[640 * 512];   // [w_mlp1 ; w_res]

__device__ __forceinline__ void cvt_hl(float x, __half& h, __half& l) {
    h = __float2half_rn(x);
    l = __float2half_rn(x - __half2float(h));
}

// ---------------- knn dtype detection + convert ----------------
__global__ void k_detect(const void* __restrict__ knn) {
    const long long* p = (const long long*)knn;
    const int total = NPTS * KNB / 2;
    int local = 0;
    for (int i = blockIdx.x * blockDim.x + threadIdx.x; i < total; i += gridDim.x * blockDim.x) {
        long long v = p[i];
        if (v < 0 || v >= NPTS) local = 1;
    }
    if (local) atomicOr(&d_knn_bad, 1);
}

__global__ void k_cvt(const void* __restrict__ knn) {
    int i = blockIdx.x * blockDim.x + threadIdx.x;
    if (i >= NPTS * KNB) return;
    if (d_knn_bad)
        d_knn32[i] = ((const int*)knn)[i];
    else
        d_knn32[i] = (int)((const long long*)knn)[i];
}

// ---------------- weight hi/lo planes ----------------
__global__ void k_wcvt(const float* __restrict__ w_mlp2, const float* __restrict__ w_mlp1,
                       const float* __restrict__ w_res) {
    int i = blockIdx.x * blockDim.x + threadIdx.x;
    if (i >= 640 * 512) return;
    __half h, l;
    if (i < 512 * 512) {
        cvt_hl(w_mlp2[i], h, l);
        d_w2h[i] = h; d_w2l[i] = l;
    }
    float v = (i < 128 * 512) ? w_mlp1[i] : w_res[i - 128 * 512];
    cvt_hl(v, h, l);
    d_wch[i] = h; d_wcl[i] = l;
}

// ---------------- prep: geo mean ----------------
__global__ void k_prep(const float* __restrict__ inp) {
    int n = blockIdx.x * blockDim.x + threadIdx.x;
    if (n >= NPTS) return;
    float xi = inp[3 * n + 0], yi = inp[3 * n + 1], zi = inp[3 * n + 2];
    float sx = 0.f, sy = 0.f, sz = 0.f, sn = 0.f;
#pragma unroll
    for (int k = 0; k < KNB; k++) {
        int j = d_knn32[n * KNB + k];
        float dx = xi - inp[3 * j + 0];
        float dy = yi - inp[3 * j + 1];
        float dz = zi - inp[3 * j + 2];
        sx += dx; sy += dy; sz += dz;
        sn += sqrtf(dx * dx + dy * dy + dz * dz);
    }
    const float s = 1.0f / KNB;
    d_geo[n * 4 + 0] = sx * s;
    d_geo[n * 4 + 1] = sy * s;
    d_geo[n * 4 + 2] = sz * s;
    d_geo[n * 4 + 3] = sn * s;
}

// ---------------- tiny geo linears + vec tail ----------------
__global__ void __launch_bounds__(256) k_smallg(
        const float* __restrict__ w_lfa1, const float* __restrict__ b_lfa1,
        const float* __restrict__ w_lfa2, const float* __restrict__ b_lfa2,
        const float* __restrict__ w_mlp2, const float* __restrict__ b_mlp1,
        const float* __restrict__ b_mlp2, const float* __restrict__ b_res) {
    int tid = threadIdx.x;
    if (blockIdx.x == 256) {
        int j = tid * 2;
        if (j < 512) {
#pragma unroll
            for (int t = 0; t < 2; t++) {
                int jj = j + t;
                d_bsum[jj] = b_mlp2[jj] + b_res[jj];
                float s = 0.f;
#pragma unroll 8
                for (int c = 0; c < 128; c++) s += w_mlp2[jj * 512 + 384 + c] * b_mlp1[c];
                d_dv[jj] = s;
            }
        }
        return;
    }
    __shared__ float s_w2[256 * 4], s_b2[256], s_w1[128 * 4], s_b1[128];
    for (int i = tid; i < 1024; i += 256) s_w2[i] = w_lfa2[i];
    for (int i = tid; i < 512;  i += 256) s_w1[i] = w_lfa1[i];
    for (int i = tid; i < 256;  i += 256) s_b2[i] = b_lfa2[i];
    if (tid < 128) s_b1[tid] = b_lfa1[tid];
    __syncthreads();
    int wid = tid >> 5, lane = tid & 31;
#pragma unroll 1
    for (int p = 0; p < 8; p++) {
        int n = (blockIdx.x * 8 + wid) * 8 + p;
        float4 g = *(const float4*)(d_geo + n * 4);
#pragma unroll
        for (int t = 0; t < 2; t++) {
            int j0 = t * 128 + lane * 4;
            float r[4];
#pragma unroll
            for (int u = 0; u < 4; u++) {
                int j = j0 + u;
                r[u] = s_b2[j] + g.x * s_w2[j * 4 + 0] + g.y * s_w2[j * 4 + 1]
                               + g.z * s_w2[j * 4 + 2] + g.w * s_w2[j * 4 + 3];
            }
            size_t o = (size_t)n * 384 + j0;
            *(__half2*)(d_Gcf + o)     = __floats2half2_rn(r[0], r[1]);
            *(__half2*)(d_Gcf + o + 2) = __floats2half2_rn(r[2], r[3]);
        }
        {
            int j0 = lane * 4;
            float r[4];
#pragma unroll
            for (int u = 0; u < 4; u++) {
                int j = j0 + u;
                r[u] = s_b1[j] + g.x * s_w1[j * 4 + 0] + g.y * s_w1[j * 4 + 1]
                               + g.z * s_w1[j * 4 + 2] + g.w * s_w1[j * 4 + 3];
            }
            *(float4*)(d_G1 + (size_t)n * 128 + j0) = make_float4(r[0], r[1], r[2], r[3]);
        }
    }
}

// ---------------- gather-mean kernels (one warp per point) ----------------
__global__ void __launch_bounds__(256) k_gather0() {
    int t = blockIdx.x * blockDim.x + threadIdx.x;
    int n = t >> 5; if (n >= NPTS) return;
    int lane = t & 31;
    const int* kn = d_knn32 + n * KNB;
    float a[4] = {};
#pragma unroll
    for (int k = 0; k < KNB; k++) {
        float4 v = *(const float4*)(d_G1 + (size_t)kn[k] * 128 + lane * 4);
        a[0] += v.x; a[1] += v.y; a[2] += v.z; a[3] += v.w;
    }
    const float s = 1.0f / KNB;
    size_t o = (size_t)n * 384 + 256 + lane * 4;
    *(__half2*)(d_Gcf + o)     = __floats2half2_rn(a[0] * s, a[1] * s);
    *(__half2*)(d_Gcf + o + 2) = __floats2half2_rn(a[2] * s, a[3] * s);
}

__global__ void __launch_bounds__(256) k_gather1() {
    int t = blockIdx.x * blockDim.x + threadIdx.x;
    int n = t >> 5; if (n >= NPTS) return;
    int lane = t & 31;
    const int* kn = d_knn32 + n * KNB;
    float a[4] = {};
#pragma unroll
    for (int k = 0; k < KNB; k++) {
        float4 v = *(const float4*)(d_xr + (size_t)kn[k] * 640 + lane * 4);
        a[0] += v.x; a[1] += v.y; a[2] += v.z; a[3] += v.w;
    }
    const float s = 1.0f / KNB;
    *(float4*)(d_ax1 + (size_t)n * 128 + lane * 4) =
        make_float4(a[0] * s, a[1] * s, a[2] * s, a[3] * s);
}

__global__ void __launch_bounds__(256) k_gather2() {
    int t = blockIdx.x * blockDim.x + threadIdx.x;
    int n = t >> 5; if (n >= NPTS) return;
    int lane = t & 31;
    const int* kn = d_knn32 + n * KNB;
    float a[4] = {};
#pragma unroll
    for (int k = 0; k < KNB; k++) {
        float4 v = *(const float4*)(d_ax1 + (size_t)kn[k] * 128 + lane * 4);
        a[0] += v.x; a[1] += v.y; a[2] += v.z; a[3] += v.w;
    }
    const float s = 1.0f / KNB;
    size_t o = (size_t)n * 128 + lane * 4;
    *(__half2*)(d_aaxf + o)     = __floats2half2_rn(a[0] * s, a[1] * s);
    *(__half2*)(d_aaxf + o + 2) = __floats2half2_rn(a[2] * s, a[3] * s);
}

// ================= fp16x2 tensor-core GEMM core (HMMA mma.sync) =================
// Tile 128x128x32, 256 threads = 8 warps (4 M x 2 N). Warp tile 32x64.
// A: activations, single fp16 plane. B: weights, hi/lo fp16 planes.
// C = A*Bh + A*Bl, fp32 accum. 2 MMAs per (k16, mi, ni) instead of 3.
__device__ __forceinline__ void mma16816(float* c, const unsigned* a, unsigned b0, unsigned b1) {
    asm volatile(
        "mma.sync.aligned.m16n8k16.row.col.f32.f16.f16.f32 "
        "{%0,%1,%2,%3}, {%4,%5,%6,%7}, {%8,%9}, {%0,%1,%2,%3};"
        : "+f"(c[0]), "+f"(c[1]), "+f"(c[2]), "+f"(c[3])
        : "r"(a[0]), "r"(a[1]), "r"(a[2]), "r"(a[3]), "r"(b0), "r"(b1));
}

__device__ __forceinline__ void cp16(__half* s, const __half* g) {
    unsigned sa = (unsigned)__cvta_generic_to_shared(s);
    asm volatile("cp.async.cg.shared.global [%0], [%1], 16;" :: "r"(sa), "l"(g));
}

#define PLANE (128 * ASTR)
#define GEMM_SMEM (2 * 3 * PLANE * 2)   // 2 stages x 3 planes x (128*ASTR halfs) = 61440 B

__device__ __forceinline__ void ld_stage(__half* s,
        const __half* A, int lda, const __half* Bh, const __half* Bl, int ldb,
        int k0, int tid) {
#pragma unroll
    for (int i = 0; i < 2; i++) {
        int chunk = tid + i * 256;       // 0..511
        int r = chunk >> 2, c8 = (chunk & 3) * 8;
        cp16(s + 0 * PLANE + r * ASTR + c8, A  + (size_t)r * lda + k0 + c8);
        cp16(s + 1 * PLANE + r * ASTR + c8, Bh + (size_t)r * ldb + k0 + c8);
        cp16(s + 2 * PLANE + r * ASTR + c8, Bl + (size_t)r * ldb + k0 + c8);
    }
}

__device__ __forceinline__ void gemm_mma(
        const __half* __restrict__ A, int lda,
        const __half* __restrict__ Bh, const __half* __restrict__ Bl, int ldb,
        int K, float (&acc)[2][8][4]) {
    extern __shared__ __half smdyn[];
    const int tid = threadIdx.x;
    const int lane = tid & 31, wid = tid >> 5;
    const int warp_m = wid & 3, warp_n = wid >> 2;
    const int grp = lane >> 2, tig = lane & 3;
    const int nk = K / 32;

    ld_stage(smdyn, A, lda, Bh, Bl, ldb, 0, tid);
    asm volatile("cp.async.commit_group;");
    for (int t = 0; t < nk; t++) {
        int st = t & 1;
        if (t + 1 < nk) {
            ld_stage(smdyn + (st ^ 1) * 3 * PLANE, A, lda, Bh, Bl, ldb, (t + 1) * 32, tid);
            asm volatile("cp.async.commit_group;");
            asm volatile("cp.async.wait_group 1;");
        } else {
            asm volatile("cp.async.wait_group 0;");
        }
        __syncthreads();
        const __half* sA  = smdyn + st * 3 * PLANE;
        const __half* sBh = sA + PLANE;
        const __half* sBl = sA + 2 * PLANE;
#pragma unroll
        for (int ks = 0; ks < 32; ks += 16) {
            unsigned af[2][4];
#pragma unroll
            for (int mi = 0; mi < 2; mi++) {
                int r = warp_m * 32 + mi * 16 + grp;
                const __half* pa = sA + r * ASTR + ks + 2 * tig;
                af[mi][0] = *(const unsigned*)(pa);
                af[mi][1] = *(const unsigned*)(pa + 8 * ASTR);
                af[mi][2] = *(const unsigned*)(pa + 8);
                af[mi][3] = *(const unsigned*)(pa + 8 * ASTR + 8);
            }
#pragma unroll
            for (int ni = 0; ni < 8; ni++) {
                int r = warp_n * 64 + ni * 8 + grp;
                const __half* ph = sBh + r * ASTR + ks + 2 * tig;
                const __half* pl = sBl + r * ASTR + ks + 2 * tig;
                unsigned bh0 = *(const unsigned*)(ph);
                unsigned bh1 = *(const unsigned*)(ph + 8);
                unsigned bl0 = *(const unsigned*)(pl);
                unsigned bl1 = *(const unsigned*)(pl + 8);
#pragma unroll
                for (int mi = 0; mi < 2; mi++) {
                    mma16816(acc[mi][ni], af[mi], bh0, bh1);
                    mma16816(acc[mi][ni], af[mi], bl0, bl1);
                }
            }
        }
        __syncthreads();
    }
}

#define EPILOG_COORDS() \
    const int lane = threadIdx.x & 31, wid = threadIdx.x >> 5; \
    const int warp_m = wid & 3, warp_n = wid >> 2; \
    const int grp = lane >> 4; (void)grp; \
    const int grp4 = lane >> 2, tig = lane & 3;

// ---------------- GEMM C0: Gcat @ W2[:, :384]^T + bsum ; fa = C0 + dv (+ fp16 plane) ----------------
__global__ void __launch_bounds__(256, 2) k_gemmC0() {
    float acc[2][8][4] = {};
    gemm_mma(d_Gcf + (size_t)blockIdx.x * 128 * 384, 384,
             d_w2h + (size_t)blockIdx.y * 128 * 512, d_w2l + (size_t)blockIdx.y * 128 * 512, 512,
             384, acc);
    EPILOG_COORDS();
#pragma unroll
    for (int mi = 0; mi < 2; mi++) {
#pragma unroll
        for (int ni = 0; ni < 8; ni++) {
            int r0 = blockIdx.x * 128 + warp_m * 32 + mi * 16 + grp4;
            int cc = blockIdx.y * 128 + warp_n * 64 + ni * 8 + tig * 2;
            float2 bs = *(const float2*)(d_bsum + cc);
            float2 dv = *(const float2*)(d_dv + cc);
            float* a = acc[mi][ni];
#pragma unroll
            for (int h2 = 0; h2 < 2; h2++) {
                int r = r0 + h2 * 8;
                size_t o = (size_t)r * 512 + cc;
                float c0 = a[2 * h2 + 0] + bs.x, c1 = a[2 * h2 + 1] + bs.y;
                *(float2*)(d_C0 + o) = make_float2(c0, c1);
                float f0 = c0 + dv.x, f1 = c1 + dv.y;
                *(float2*)(d_fa + o) = make_float2(f0, f1);
                *(__half2*)(d_faf + o) = __floats2half2_rn(f0, f1);
            }
        }
    }
}

// ---------------- GEMM1: xr = f @ [w_mlp1 ; w_res]^T  (N=640, K=512) ----------------
__global__ void __launch_bounds__(256, 2) k_gemm1(int fsel, const float* __restrict__ b_mlp1) {
    const __half* Af = (fsel ? d_fbf : d_faf) + (size_t)blockIdx.x * 128 * 512;
    float acc[2][8][4] = {};
    gemm_mma(Af, 512,
             d_wch + (size_t)blockIdx.y * 128 * 512, d_wcl + (size_t)blockIdx.y * 128 * 512, 512,
             512, acc);
    EPILOG_COORDS();
#pragma unroll
    for (int mi = 0; mi < 2; mi++) {
#pragma unroll
        for (int ni = 0; ni < 8; ni++) {
            int r0 = blockIdx.x * 128 + warp_m * 32 + mi * 16 + grp4;
            int cc = blockIdx.y * 128 + warp_n * 64 + ni * 8 + tig * 2;
            float2 bs = make_float2(0.f, 0.f);
            if (blockIdx.y == 0) bs = *(const float2*)(b_mlp1 + (cc & 127));
            float* a = acc[mi][ni];
            *(float2*)(d_xr + (size_t)r0 * 640 + cc)       = make_float2(a[0] + bs.x, a[1] + bs.y);
            *(float2*)(d_xr + (size_t)(r0 + 8) * 640 + cc) = make_float2(a[2] + bs.x, a[3] + bs.y);
        }
    }
}

// ---------------- GEMM2: f_new = C0 + f + r + aax1 @ W2[:,384:512]^T  (K=128) ----------------
__global__ void __launch_bounds__(256, 2) k_gemm2(int fsel, int dsel, float* __restrict__ outp) {
    const float* f = fsel ? d_fb : d_fa;
    float* dst = (dsel == 0) ? d_fb : (dsel == 1) ? d_fa : outp;
    __half* dstf = (dsel == 0) ? d_fbf : d_faf;
    float acc[2][8][4] = {};
    gemm_mma(d_aaxf + (size_t)blockIdx.x * 128 * 128, 128,
             d_w2h + (size_t)blockIdx.y * 128 * 512 + 384,
             d_w2l + (size_t)blockIdx.y * 128 * 512 + 384, 512,
             128, acc);
    EPILOG_COORDS();
#pragma unroll
    for (int mi = 0; mi < 2; mi++) {
#pragma unroll
        for (int ni = 0; ni < 8; ni++) {
            int r0 = blockIdx.x * 128 + warp_m * 32 + mi * 16 + grp4;
            int cc = blockIdx.y * 128 + warp_n * 64 + ni * 8 + tig * 2;
            float* a = acc[mi][ni];
#pragma unroll
            for (int h2 = 0; h2 < 2; h2++) {
                int r = r0 + h2 * 8;
                size_t o = (size_t)r * 512 + cc;
                float2 c0 = *(const float2*)(d_C0 + o);
                float2 fv = *(const float2*)(f + o);
                float2 rv = *(const float2*)(d_xr + (size_t)r * 640 + 128 + cc);
                float v0 = a[2 * h2 + 0] + c0.x + fv.x + rv.x;
                float v1 = a[2 * h2 + 1] + c0.y + fv.y + rv.y;
                *(float2*)(dst + o) = make_float2(v0, v1);
                if (dsel != 2)
                    *(__half2*)(dstf + o) = __floats2half2_rn(v0, v1);
            }
        }
    }
}

// ---------------- launch ----------------
extern "C" void kernel_launch(void* const* d_in, const int* in_sizes, int n_in,
                              void* d_out, int out_size) {
    const float* inputs = (const float*)d_in[0];
    const void*  knn    = d_in[1];
    const float* w_mlp1 = (const float*)d_in[2];
    const float* b_mlp1 = (const float*)d_in[3];
    const float* w_lfa1 = (const float*)d_in[4];
    const float* b_lfa1 = (const float*)d_in[5];
    const float* w_lfa2 = (const float*)d_in[6];
    const float* b_lfa2 = (const float*)d_in[7];
    const float* w_mlp2 = (const float*)d_in[8];
    const float* b_mlp2 = (const float*)d_in[9];
    const float* w_res  = (const float*)d_in[10];
    const float* b_res  = (const float*)d_in[11];
    float* out = (float*)d_out;

    static int smem_set = 0;
    if (!smem_set) {
        cudaFuncSetAttribute(k_gemmC0, cudaFuncAttributeMaxDynamicSharedMemorySize, GEMM_SMEM);
        cudaFuncSetAttribute(k_gemm1,  cudaFuncAttributeMaxDynamicSharedMemorySize, GEMM_SMEM);
        cudaFuncSetAttribute(k_gemm2,  cudaFuncAttributeMaxDynamicSharedMemorySize, GEMM_SMEM);
        smem_set = 1;
    }

    k_detect<<<128, 256>>>(knn);
    k_cvt<<<(NPTS * KNB) / 256, 256>>>(knn);
    k_wcvt<<<(640 * 512) / 256, 256>>>(w_mlp2, w_mlp1, w_res);
    k_prep<<<NPTS / 256, 256>>>(inputs);
    k_smallg<<<257, 256>>>(w_lfa1, b_lfa1, w_lfa2, b_lfa2,
                           w_mlp2, b_mlp1, b_mlp2, b_res);
    k_gather0<<<(NPTS * 32) / 256, 256>>>();
    dim3 gC0(128, 4);
    k_gemmC0<<<gC0, 256, GEMM_SMEM>>>();

    int fsel = 0;
    for (int it = 0; it < 3; it++) {
        dim3 g1(128, 5);
        k_gemm1<<<g1, 256, GEMM_SMEM>>>(fsel, b_mlp1);
        k_gather1<<<(NPTS * 32) / 256, 256>>>();
        k_gather2<<<(NPTS * 32) / 256, 256>>>();
        dim3 g2(128, 4);
        int dsel = (it == 2) ? 2 : (fsel == 0 ? 0 : 1);
        k_gemm2<<<g2, 256, GEMM_SMEM>>>(fsel, dsel, out);
        fsel ^= 1;
    }
    (void)in_sizes; (void)n_in; (void)out_size;
}

// round 10
// speedup vs baseline: 1.3711x; 1.0624x over previous
#include <cuda_runtime.h>
#include <cuda_fp16.h>
#include <math.h>
#include <stdint.h>

#define NPTS 16384
#define KNB  16
#define ASTR 40   // smem row stride (halfs): 32 + 8 pad, conflict-free, 80B (16B aligned)

// ---------------- device scratch (static: no allocations allowed) ----------------
__device__ float d_geo[NPTS * 4];
__device__ int   d_knn32[NPTS * KNB];
__device__ int   d_knn_bad;                  // 0 => int64 knn, nonzero => int32
__device__ float d_C0[(size_t)NPTS * 512];
__device__ float d_fa[(size_t)NPTS * 512];
__device__ float d_fb[(size_t)NPTS * 512];
__device__ float d_r[(size_t)NPTS * 512];    // f @ w_res^T
__device__ float d_dv[512];
__device__ float d_bsum[512];

// fp16 planes
__device__ __half d_G1f[NPTS * 128];
__device__ __half d_x1f[NPTS * 128];
__device__ __half d_ax1f[NPTS * 128];
__device__ __half d_Gcf[(size_t)NPTS * 384];
__device__ __half d_faf[(size_t)NPTS * 512];
__device__ __half d_fbf[(size_t)NPTS * 512];
__device__ __half d_aaxf[NPTS * 128];
__device__ __half d_w2h[512 * 512], d_w2l[512 * 512];
__device__ __half d_wch[640 * 512], d_wcl[640 * 512];   // [w_mlp1 ; w_res]

__device__ __forceinline__ void cvt_hl(float x, __half& h, __half& l) {
    h = __float2half_rn(x);
    l = __float2half_rn(x - __half2float(h));
}

// ---------------- knn dtype detection + convert ----------------
__global__ void k_detect(const void* __restrict__ knn) {
    const long long* p = (const long long*)knn;
    const int total = NPTS * KNB / 2;
    int local = 0;
    for (int i = blockIdx.x * blockDim.x + threadIdx.x; i < total; i += gridDim.x * blockDim.x) {
        long long v = p[i];
        if (v < 0 || v >= NPTS) local = 1;
    }
    if (local) atomicOr(&d_knn_bad, 1);
}

__global__ void k_cvt(const void* __restrict__ knn) {
    int i = blockIdx.x * blockDim.x + threadIdx.x;
    if (i >= NPTS * KNB) return;
    if (d_knn_bad)
        d_knn32[i] = ((const int*)knn)[i];
    else
        d_knn32[i] = (int)((const long long*)knn)[i];
}

// ---------------- weight hi/lo planes ----------------
__global__ void k_wcvt(const float* __restrict__ w_mlp2, const float* __restrict__ w_mlp1,
                       const float* __restrict__ w_res) {
    int i = blockIdx.x * blockDim.x + threadIdx.x;
    if (i >= 640 * 512) return;
    __half h, l;
    if (i < 512 * 512) {
        cvt_hl(w_mlp2[i], h, l);
        d_w2h[i] = h; d_w2l[i] = l;
    }
    float v = (i < 128 * 512) ? w_mlp1[i] : w_res[i - 128 * 512];
    cvt_hl(v, h, l);
    d_wch[i] = h; d_wcl[i] = l;
}

// ---------------- prep: geo mean ----------------
__global__ void k_prep(const float* __restrict__ inp) {
    int n = blockIdx.x * blockDim.x + threadIdx.x;
    if (n >= NPTS) return;
    float xi = inp[3 * n + 0], yi = inp[3 * n + 1], zi = inp[3 * n + 2];
    float sx = 0.f, sy = 0.f, sz = 0.f, sn = 0.f;
#pragma unroll
    for (int k = 0; k < KNB; k++) {
        int j = d_knn32[n * KNB + k];
        float dx = xi - inp[3 * j + 0];
        float dy = yi - inp[3 * j + 1];
        float dz = zi - inp[3 * j + 2];
        sx += dx; sy += dy; sz += dz;
        sn += sqrtf(dx * dx + dy * dy + dz * dz);
    }
    const float s = 1.0f / KNB;
    d_geo[n * 4 + 0] = sx * s;
    d_geo[n * 4 + 1] = sy * s;
    d_geo[n * 4 + 2] = sz * s;
    d_geo[n * 4 + 3] = sn * s;
}

// ---------------- tiny geo linears + vec tail ----------------
__global__ void __launch_bounds__(256) k_smallg(
        const float* __restrict__ w_lfa1, const float* __restrict__ b_lfa1,
        const float* __restrict__ w_lfa2, const float* __restrict__ b_lfa2,
        const float* __restrict__ w_mlp2, const float* __restrict__ b_mlp1,
        const float* __restrict__ b_mlp2, const float* __restrict__ b_res) {
    int tid = threadIdx.x;
    if (blockIdx.x == 256) {
        int j = tid * 2;
        if (j < 512) {
#pragma unroll
            for (int t = 0; t < 2; t++) {
                int jj = j + t;
                d_bsum[jj] = b_mlp2[jj] + b_res[jj];
                float s = 0.f;
#pragma unroll 8
                for (int c = 0; c < 128; c++) s += w_mlp2[jj * 512 + 384 + c] * b_mlp1[c];
                d_dv[jj] = s;
            }
        }
        return;
    }
    __shared__ float s_w2[256 * 4], s_b2[256], s_w1[128 * 4], s_b1[128];
    for (int i = tid; i < 1024; i += 256) s_w2[i] = w_lfa2[i];
    for (int i = tid; i < 512;  i += 256) s_w1[i] = w_lfa1[i];
    for (int i = tid; i < 256;  i += 256) s_b2[i] = b_lfa2[i];
    if (tid < 128) s_b1[tid] = b_lfa1[tid];
    __syncthreads();
    int wid = tid >> 5, lane = tid & 31;
#pragma unroll 1
    for (int p = 0; p < 8; p++) {
        int n = (blockIdx.x * 8 + wid) * 8 + p;
        float4 g = *(const float4*)(d_geo + n * 4);
#pragma unroll
        for (int t = 0; t < 2; t++) {
            int j0 = t * 128 + lane * 4;
            float r[4];
#pragma unroll
            for (int u = 0; u < 4; u++) {
                int j = j0 + u;
                r[u] = s_b2[j] + g.x * s_w2[j * 4 + 0] + g.y * s_w2[j * 4 + 1]
                               + g.z * s_w2[j * 4 + 2] + g.w * s_w2[j * 4 + 3];
            }
            size_t o = (size_t)n * 384 + j0;
            *(__half2*)(d_Gcf + o)     = __floats2half2_rn(r[0], r[1]);
            *(__half2*)(d_Gcf + o + 2) = __floats2half2_rn(r[2], r[3]);
        }
        {
            int j0 = lane * 4;
            float r[4];
#pragma unroll
            for (int u = 0; u < 4; u++) {
                int j = j0 + u;
                r[u] = s_b1[j] + g.x * s_w1[j * 4 + 0] + g.y * s_w1[j * 4 + 1]
                               + g.z * s_w1[j * 4 + 2] + g.w * s_w1[j * 4 + 3];
            }
            size_t o = (size_t)n * 128 + j0;
            *(__half2*)(d_G1f + o)     = __floats2half2_rn(r[0], r[1]);
            *(__half2*)(d_G1f + o + 2) = __floats2half2_rn(r[2], r[3]);
        }
    }
}

// ---------------- gather-mean kernels (one warp per point, fp16 rows) ----------------
__device__ __forceinline__ void gather128_f16(const __half* __restrict__ src,
                                              __half* __restrict__ dst,
                                              int n, int lane) {
    const int* kn = d_knn32 + n * KNB;
    float a0 = 0.f, a1 = 0.f, a2 = 0.f, a3 = 0.f;
#pragma unroll
    for (int k = 0; k < KNB; k++) {
        uint2 v = *(const uint2*)(src + (size_t)kn[k] * 128 + lane * 4);
        __half2 p0 = *(__half2*)&v.x, p1 = *(__half2*)&v.y;
        a0 += __low2float(p0); a1 += __high2float(p0);
        a2 += __low2float(p1); a3 += __high2float(p1);
    }
    const float s = 1.0f / KNB;
    uint2 o;
    *(__half2*)&o.x = __floats2half2_rn(a0 * s, a1 * s);
    *(__half2*)&o.y = __floats2half2_rn(a2 * s, a3 * s);
    *(uint2*)(dst + (size_t)n * 128 + lane * 4) = o;
}

__global__ void __launch_bounds__(256) k_gather0() {
    int t = blockIdx.x * blockDim.x + threadIdx.x;
    int n = t >> 5; if (n >= NPTS) return;
    int lane = t & 31;
    const int* kn = d_knn32 + n * KNB;
    float a0 = 0.f, a1 = 0.f, a2 = 0.f, a3 = 0.f;
#pragma unroll
    for (int k = 0; k < KNB; k++) {
        uint2 v = *(const uint2*)(d_G1f + (size_t)kn[k] * 128 + lane * 4);
        __half2 p0 = *(__half2*)&v.x, p1 = *(__half2*)&v.y;
        a0 += __low2float(p0); a1 += __high2float(p0);
        a2 += __low2float(p1); a3 += __high2float(p1);
    }
    const float s = 1.0f / KNB;
    size_t o = (size_t)n * 384 + 256 + lane * 4;
    *(__half2*)(d_Gcf + o)     = __floats2half2_rn(a0 * s, a1 * s);
    *(__half2*)(d_Gcf + o + 2) = __floats2half2_rn(a2 * s, a3 * s);
}

__global__ void __launch_bounds__(256) k_gather1() {
    int t = blockIdx.x * blockDim.x + threadIdx.x;
    int n = t >> 5; if (n >= NPTS) return;
    gather128_f16(d_x1f, d_ax1f, n, t & 31);
}

__global__ void __launch_bounds__(256) k_gather2() {
    int t = blockIdx.x * blockDim.x + threadIdx.x;
    int n = t >> 5; if (n >= NPTS) return;
    gather128_f16(d_ax1f, d_aaxf, n, t & 31);
}

// ================= fp16x2 tensor-core GEMM core (HMMA + ldmatrix) =================
// Tile 128x128x32, 256 threads = 8 warps (4 M x 2 N). Warp tile 32x64.
// A: activations fp16 plane. B: weights hi/lo fp16. C = A*Bh + A*Bl, fp32 accum.
__device__ __forceinline__ void mma16816(float* c, const unsigned* a, unsigned b0, unsigned b1) {
    asm volatile(
        "mma.sync.aligned.m16n8k16.row.col.f32.f16.f16.f32 "
        "{%0,%1,%2,%3}, {%4,%5,%6,%7}, {%8,%9}, {%0,%1,%2,%3};"
        : "+f"(c[0]), "+f"(c[1]), "+f"(c[2]), "+f"(c[3])
        : "r"(a[0]), "r"(a[1]), "r"(a[2]), "r"(a[3]), "r"(b0), "r"(b1));
}

#define LDMX4(d, addr) \
    asm volatile("ldmatrix.sync.aligned.m8n8.x4.shared.b16 {%0,%1,%2,%3}, [%4];" \
        : "=r"((d)[0]), "=r"((d)[1]), "=r"((d)[2]), "=r"((d)[3]) : "r"(addr))

__device__ __forceinline__ void cp16(__half* s, const __half* g) {
    unsigned sa = (unsigned)__cvta_generic_to_shared(s);
    asm volatile("cp.async.cg.shared.global [%0], [%1], 16;" :: "r"(sa), "l"(g));
}

#define PLANE (128 * ASTR)
#define GEMM_SMEM (2 * 3 * PLANE * 2)   // 2 stages x 3 planes x (128*ASTR halfs) = 61440 B

__device__ __forceinline__ void ld_stage(__half* s,
        const __half* A, int lda, const __half* Bh, const __half* Bl, int ldb,
        int k0, int tid) {
#pragma unroll
    for (int i = 0; i < 2; i++) {
        int chunk = tid + i * 256;       // 0..511
        int r = chunk >> 2, c8 = (chunk & 3) * 8;
        cp16(s + 0 * PLANE + r * ASTR + c8, A  + (size_t)r * lda + k0 + c8);
        cp16(s + 1 * PLANE + r * ASTR + c8, Bh + (size_t)r * ldb + k0 + c8);
        cp16(s + 2 * PLANE + r * ASTR + c8, Bl + (size_t)r * ldb + k0 + c8);
    }
}

__device__ __forceinline__ void gemm_mma(
        const __half* __restrict__ A, int lda,
        const __half* __restrict__ Bh, const __half* __restrict__ Bl, int ldb,
        int K, float (&acc)[2][8][4]) {
    extern __shared__ __half smdyn[];
    const int tid = threadIdx.x;
    const int lane = tid & 31, wid = tid >> 5;
    const int warp_m = wid & 3, warp_n = wid >> 2;
    const int nk = K / 32;
    const unsigned smbase = (unsigned)__cvta_generic_to_shared(smdyn);

    // ldmatrix per-lane element offsets (in halfs), excluding ks / mi / p terms
    const int a_off = (warp_m * 32 + ((lane >> 3) & 1) * 8 + (lane & 7)) * ASTR
                      + ((lane >> 4) * 8);
    const int b_off = (warp_n * 64 + ((lane >> 4) & 1) * 8 + (lane & 7)) * ASTR
                      + (((lane >> 3) & 1) * 8);

    ld_stage(smdyn, A, lda, Bh, Bl, ldb, 0, tid);
    asm volatile("cp.async.commit_group;");
    for (int t = 0; t < nk; t++) {
        int st = t & 1;
        if (t + 1 < nk) {
            ld_stage(smdyn + (st ^ 1) * 3 * PLANE, A, lda, Bh, Bl, ldb, (t + 1) * 32, tid);
            asm volatile("cp.async.commit_group;");
            asm volatile("cp.async.wait_group 1;");
        } else {
            asm volatile("cp.async.wait_group 0;");
        }
        __syncthreads();
        const unsigned aB  = smbase + (st * 3 * PLANE) * 2;
        const unsigned bhB = aB + PLANE * 2;
        const unsigned blB = aB + 2 * PLANE * 2;
#pragma unroll
        for (int ks = 0; ks < 32; ks += 16) {
            unsigned af[2][4];
            LDMX4(af[0], aB + (unsigned)(a_off + ks) * 2);
            LDMX4(af[1], aB + (unsigned)(a_off + 16 * ASTR + ks) * 2);
#pragma unroll
            for (int p = 0; p < 4; p++) {
                unsigned bh[4], bl[4];
                unsigned bo = (unsigned)(b_off + p * 16 * ASTR + ks) * 2;
                LDMX4(bh, bhB + bo);
                LDMX4(bl, blB + bo);
                mma16816(acc[0][2 * p],     af[0], bh[0], bh[1]);
                mma16816(acc[1][2 * p],     af[1], bh[0], bh[1]);
                mma16816(acc[0][2 * p],     af[0], bl[0], bl[1]);
                mma16816(acc[1][2 * p],     af[1], bl[0], bl[1]);
                mma16816(acc[0][2 * p + 1], af[0], bh[2], bh[3]);
                mma16816(acc[1][2 * p + 1], af[1], bh[2], bh[3]);
                mma16816(acc[0][2 * p + 1], af[0], bl[2], bl[3]);
                mma16816(acc[1][2 * p + 1], af[1], bl[2], bl[3]);
            }
        }
        __syncthreads();
    }
}

#define EPILOG_COORDS() \
    const int lane = threadIdx.x & 31, wid = threadIdx.x >> 5; \
    const int warp_m = wid & 3, warp_n = wid >> 2; \
    const int grp4 = lane >> 2, tig = lane & 3;

// ---------------- GEMM C0: Gcat @ W2[:, :384]^T + bsum ; fa = C0 + dv (+ fp16 plane) ----------------
__global__ void __launch_bounds__(256, 2) k_gemmC0() {
    float acc[2][8][4] = {};
    gemm_mma(d_Gcf + (size_t)blockIdx.x * 128 * 384, 384,
             d_w2h + (size_t)blockIdx.y * 128 * 512, d_w2l + (size_t)blockIdx.y * 128 * 512, 512,
             384, acc);
    EPILOG_COORDS();
#pragma unroll
    for (int mi = 0; mi < 2; mi++) {
#pragma unroll
        for (int ni = 0; ni < 8; ni++) {
            int r0 = blockIdx.x * 128 + warp_m * 32 + mi * 16 + grp4;
            int cc = blockIdx.y * 128 + warp_n * 64 + ni * 8 + tig * 2;
            float2 bs = *(const float2*)(d_bsum + cc);
            float2 dv = *(const float2*)(d_dv + cc);
            float* a = acc[mi][ni];
#pragma unroll
            for (int h2 = 0; h2 < 2; h2++) {
                int r = r0 + h2 * 8;
                size_t o = (size_t)r * 512 + cc;
                float c0 = a[2 * h2 + 0] + bs.x, c1 = a[2 * h2 + 1] + bs.y;
                *(float2*)(d_C0 + o) = make_float2(c0, c1);
                float f0 = c0 + dv.x, f1 = c1 + dv.y;
                *(float2*)(d_fa + o) = make_float2(f0, f1);
                *(__half2*)(d_faf + o) = __floats2half2_rn(f0, f1);
            }
        }
    }
}

// ---------------- GEMM1: [x1 | r] = f @ [w_mlp1 ; w_res]^T  (N=640, K=512) ----------------
__global__ void __launch_bounds__(256, 2) k_gemm1(int fsel, const float* __restrict__ b_mlp1) {
    const __half* Af = (fsel ? d_fbf : d_faf) + (size_t)blockIdx.x * 128 * 512;
    float acc[2][8][4] = {};
    gemm_mma(Af, 512,
             d_wch + (size_t)blockIdx.y * 128 * 512, d_wcl + (size_t)blockIdx.y * 128 * 512, 512,
             512, acc);
    EPILOG_COORDS();
#pragma unroll
    for (int mi = 0; mi < 2; mi++) {
#pragma unroll
        for (int ni = 0; ni < 8; ni++) {
            int r0 = blockIdx.x * 128 + warp_m * 32 + mi * 16 + grp4;
            int cl = warp_n * 64 + ni * 8 + tig * 2;       // 0..127 within this y-block
            float* a = acc[mi][ni];
            if (blockIdx.y == 0) {
                float2 bs = *(const float2*)(b_mlp1 + cl);
#pragma unroll
                for (int h2 = 0; h2 < 2; h2++) {
                    int r = r0 + h2 * 8;
                    *(__half2*)(d_x1f + (size_t)r * 128 + cl) =
                        __floats2half2_rn(a[2 * h2 + 0] + bs.x, a[2 * h2 + 1] + bs.y);
                }
            } else {
                int cc = (blockIdx.y - 1) * 128 + cl;
#pragma unroll
                for (int h2 = 0; h2 < 2; h2++) {
                    int r = r0 + h2 * 8;
                    *(float2*)(d_r + (size_t)r * 512 + cc) =
                        make_float2(a[2 * h2 + 0], a[2 * h2 + 1]);
                }
            }
        }
    }
}

// ---------------- GEMM2: f_new = C0 + f + r + aax1 @ W2[:,384:512]^T  (K=128) ----------------
__global__ void __launch_bounds__(256, 2) k_gemm2(int fsel, int dsel, float* __restrict__ outp) {
    const float* f = fsel ? d_fb : d_fa;
    float* dst = (dsel == 0) ? d_fb : (dsel == 1) ? d_fa : outp;
    __half* dstf = (dsel == 0) ? d_fbf : d_faf;
    float acc[2][8][4] = {};
    gemm_mma(d_aaxf + (size_t)blockIdx.x * 128 * 128, 128,
             d_w2h + (size_t)blockIdx.y * 128 * 512 + 384,
             d_w2l + (size_t)blockIdx.y * 128 * 512 + 384, 512,
             128, acc);
    EPILOG_COORDS();
#pragma unroll
    for (int mi = 0; mi < 2; mi++) {
#pragma unroll
        for (int ni = 0; ni < 8; ni++) {
            int r0 = blockIdx.x * 128 + warp_m * 32 + mi * 16 + grp4;
            int cc = blockIdx.y * 128 + warp_n * 64 + ni * 8 + tig * 2;
            float* a = acc[mi][ni];
#pragma unroll
            for (int h2 = 0; h2 < 2; h2++) {
                int r = r0 + h2 * 8;
                size_t o = (size_t)r * 512 + cc;
                float2 c0 = *(const float2*)(d_C0 + o);
                float2 fv = *(const float2*)(f + o);
                float2 rv = *(const float2*)(d_r + o);
                float v0 = a[2 * h2 + 0] + c0.x + fv.x + rv.x;
                float v1 = a[2 * h2 + 1] + c0.y + fv.y + rv.y;
                *(float2*)(dst + o) = make_float2(v0, v1);
                if (dsel != 2)
                    *(__half2*)(dstf + o) = __floats2half2_rn(v0, v1);
            }
        }
    }
}

// ---------------- launch ----------------
extern "C" void kernel_launch(void* const* d_in, const int* in_sizes, int n_in,
                              void* d_out, int out_size) {
    const float* inputs = (const float*)d_in[0];
    const void*  knn    = d_in[1];
    const float* w_mlp1 = (const float*)d_in[2];
    const float* b_mlp1 = (const float*)d_in[3];
    const float* w_lfa1 = (const float*)d_in[4];
    const float* b_lfa1 = (const float*)d_in[5];
    const float* w_lfa2 = (const float*)d_in[6];
    const float* b_lfa2 = (const float*)d_in[7];
    const float* w_mlp2 = (const float*)d_in[8];
    const float* b_mlp2 = (const float*)d_in[9];
    const float* w_res  = (const float*)d_in[10];
    const float* b_res  = (const float*)d_in[11];
    float* out = (float*)d_out;

    static int smem_set = 0;
    if (!smem_set) {
        cudaFuncSetAttribute(k_gemmC0, cudaFuncAttributeMaxDynamicSharedMemorySize, GEMM_SMEM);
        cudaFuncSetAttribute(k_gemm1,  cudaFuncAttributeMaxDynamicSharedMemorySize, GEMM_SMEM);
        cudaFuncSetAttribute(k_gemm2,  cudaFuncAttributeMaxDynamicSharedMemorySize, GEMM_SMEM);
        smem_set = 1;
    }

    k_detect<<<128, 256>>>(knn);
    k_cvt<<<(NPTS * KNB) / 256, 256>>>(knn);
    k_wcvt<<<(640 * 512) / 256, 256>>>(w_mlp2, w_mlp1, w_res);
    k_prep<<<NPTS / 256, 256>>>(inputs);
    k_smallg<<<257, 256>>>(w_lfa1, b_lfa1, w_lfa2, b_lfa2,
                           w_mlp2, b_mlp1, b_mlp2, b_res);
    k_gather0<<<(NPTS * 32) / 256, 256>>>();
    dim3 gC0(128, 4);
    k_gemmC0<<<gC0, 256, GEMM_SMEM>>>();

    int fsel = 0;
    for (int it = 0; it < 3; it++) {
        dim3 g1(128, 5);
        k_gemm1<<<g1, 256, GEMM_SMEM>>>(fsel, b_mlp1);
        k_gather1<<<(NPTS * 32) / 256, 256>>>();
        k_gather2<<<(NPTS * 32) / 256, 256>>>();
        dim3 g2(128, 4);
        int dsel = (it == 2) ? 2 : (fsel == 0 ? 0 : 1);
        k_gemm2<<<g2, 256, GEMM_SMEM>>>(fsel, dsel, out);
        fsel ^= 1;
    }
    (void)in_sizes; (void)n_in; (void)out_size;
}

// round 11
// speedup vs baseline: 1.5318x; 1.1172x over previous
#include <cuda_runtime.h>
#include <cuda_fp16.h>
#include <math.h>
#include <stdint.h>

#define NPTS 16384
#define KNB  16
#define ASTR 40   // smem row stride (halfs): 32 + 8 pad, conflict-free, 80B (16B aligned)

// ---------------- device scratch (static: no allocations allowed) ----------------
__device__ float d_geo[NPTS * 4];
__device__ int   d_knn32[NPTS * KNB];
__device__ int   d_knn_bad;                  // 0 => int64 knn, nonzero => int32
__device__ float d_C0[(size_t)NPTS * 512];
__device__ float d_fa[(size_t)NPTS * 512];
__device__ float d_fb[(size_t)NPTS * 512];
__device__ float d_r[(size_t)NPTS * 512];    // f @ w_res^T
__device__ float d_dv[512];
__device__ float d_bsum[512];

// fp16 planes
__device__ __half d_G1f[NPTS * 128];
__device__ __half d_x1f[NPTS * 128];
__device__ __half d_ax1f[NPTS * 128];
__device__ __half d_Gcf[(size_t)NPTS * 384];
__device__ __half d_faf[(size_t)NPTS * 512];
__device__ __half d_fbf[(size_t)NPTS * 512];
__device__ __half d_aaxf[NPTS * 128];
__device__ __half d_w2h[512 * 512], d_w2l[512 * 512];
__device__ __half d_wch[640 * 512];                 // [w_mlp1 ; w_res] hi
__device__ __half d_wcl[128 * 512];                 // w_mlp1 lo only (w_res is single-plane)

__device__ __forceinline__ void cvt_hl(float x, __half& h, __half& l) {
    h = __float2half_rn(x);
    l = __float2half_rn(x - __half2float(h));
}

// ---------------- knn dtype detection + convert ----------------
__global__ void k_detect(const void* __restrict__ knn) {
    const long long* p = (const long long*)knn;
    const int total = NPTS * KNB / 2;
    int local = 0;
    for (int i = blockIdx.x * blockDim.x + threadIdx.x; i < total; i += gridDim.x * blockDim.x) {
        long long v = p[i];
        if (v < 0 || v >= NPTS) local = 1;
    }
    if (local) atomicOr(&d_knn_bad, 1);
}

__global__ void k_cvt(const void* __restrict__ knn) {
    int i = blockIdx.x * blockDim.x + threadIdx.x;
    if (i >= NPTS * KNB) return;
    if (d_knn_bad)
        d_knn32[i] = ((const int*)knn)[i];
    else
        d_knn32[i] = (int)((const long long*)knn)[i];
}

// ---------------- weight planes ----------------
__global__ void k_wcvt(const float* __restrict__ w_mlp2, const float* __restrict__ w_mlp1,
                       const float* __restrict__ w_res) {
    int i = blockIdx.x * blockDim.x + threadIdx.x;
    if (i >= 640 * 512) return;
    __half h, l;
    if (i < 512 * 512) {
        cvt_hl(w_mlp2[i], h, l);
        d_w2h[i] = h; d_w2l[i] = l;
    }
    float v = (i < 128 * 512) ? w_mlp1[i] : w_res[i - 128 * 512];
    cvt_hl(v, h, l);
    d_wch[i] = h;
    if (i < 128 * 512) d_wcl[i] = l;
}

// ---------------- prep: geo mean ----------------
__global__ void k_prep(const float* __restrict__ inp) {
    int n = blockIdx.x * blockDim.x + threadIdx.x;
    if (n >= NPTS) return;
    float xi = inp[3 * n + 0], yi = inp[3 * n + 1], zi = inp[3 * n + 2];
    float sx = 0.f, sy = 0.f, sz = 0.f, sn = 0.f;
#pragma unroll
    for (int k = 0; k < KNB; k++) {
        int j = d_knn32[n * KNB + k];
        float dx = xi - inp[3 * j + 0];
        float dy = yi - inp[3 * j + 1];
        float dz = zi - inp[3 * j + 2];
        sx += dx; sy += dy; sz += dz;
        sn += sqrtf(dx * dx + dy * dy + dz * dz);
    }
    const float s = 1.0f / KNB;
    d_geo[n * 4 + 0] = sx * s;
    d_geo[n * 4 + 1] = sy * s;
    d_geo[n * 4 + 2] = sz * s;
    d_geo[n * 4 + 3] = sn * s;
}

// ---------------- tiny geo linears + vec tail ----------------
__global__ void __launch_bounds__(256) k_smallg(
        const float* __restrict__ w_lfa1, const float* __restrict__ b_lfa1,
        const float* __restrict__ w_lfa2, const float* __restrict__ b_lfa2,
        const float* __restrict__ w_mlp2, const float* __restrict__ b_mlp1,
        const float* __restrict__ b_mlp2, const float* __restrict__ b_res) {
    int tid = threadIdx.x;
    if (blockIdx.x == 256) {
        int j = tid * 2;
        if (j < 512) {
#pragma unroll
            for (int t = 0; t < 2; t++) {
                int jj = j + t;
                d_bsum[jj] = b_mlp2[jj] + b_res[jj];
                float s = 0.f;
#pragma unroll 8
                for (int c = 0; c < 128; c++) s += w_mlp2[jj * 512 + 384 + c] * b_mlp1[c];
                d_dv[jj] = s;
            }
        }
        return;
    }
    __shared__ float s_w2[256 * 4], s_b2[256], s_w1[128 * 4], s_b1[128];
    for (int i = tid; i < 1024; i += 256) s_w2[i] = w_lfa2[i];
    for (int i = tid; i < 512;  i += 256) s_w1[i] = w_lfa1[i];
    for (int i = tid; i < 256;  i += 256) s_b2[i] = b_lfa2[i];
    if (tid < 128) s_b1[tid] = b_lfa1[tid];
    __syncthreads();
    int wid = tid >> 5, lane = tid & 31;
#pragma unroll 1
    for (int p = 0; p < 8; p++) {
        int n = (blockIdx.x * 8 + wid) * 8 + p;
        float4 g = *(const float4*)(d_geo + n * 4);
#pragma unroll
        for (int t = 0; t < 2; t++) {
            int j0 = t * 128 + lane * 4;
            float r[4];
#pragma unroll
            for (int u = 0; u < 4; u++) {
                int j = j0 + u;
                r[u] = s_b2[j] + g.x * s_w2[j * 4 + 0] + g.y * s_w2[j * 4 + 1]
                               + g.z * s_w2[j * 4 + 2] + g.w * s_w2[j * 4 + 3];
            }
            size_t o = (size_t)n * 384 + j0;
            *(__half2*)(d_Gcf + o)     = __floats2half2_rn(r[0], r[1]);
            *(__half2*)(d_Gcf + o + 2) = __floats2half2_rn(r[2], r[3]);
        }
        {
            int j0 = lane * 4;
            float r[4];
#pragma unroll
            for (int u = 0; u < 4; u++) {
                int j = j0 + u;
                r[u] = s_b1[j] + g.x * s_w1[j * 4 + 0] + g.y * s_w1[j * 4 + 1]
                               + g.z * s_w1[j * 4 + 2] + g.w * s_w1[j * 4 + 3];
            }
            size_t o = (size_t)n * 128 + j0;
            *(__half2*)(d_G1f + o)     = __floats2half2_rn(r[0], r[1]);
            *(__half2*)(d_G1f + o + 2) = __floats2half2_rn(r[2], r[3]);
        }
    }
}

// ---------------- gather-mean kernels (one warp per point, fp16 rows) ----------------
__device__ __forceinline__ void gather128_f16(const __half* __restrict__ src,
                                              __half* __restrict__ dst,
                                              int n, int lane) {
    const int* kn = d_knn32 + n * KNB;
    float a0 = 0.f, a1 = 0.f, a2 = 0.f, a3 = 0.f;
#pragma unroll
    for (int k = 0; k < KNB; k++) {
        uint2 v = *(const uint2*)(src + (size_t)kn[k] * 128 + lane * 4);
        __half2 p0 = *(__half2*)&v.x, p1 = *(__half2*)&v.y;
        a0 += __low2float(p0); a1 += __high2float(p0);
        a2 += __low2float(p1); a3 += __high2float(p1);
    }
    const float s = 1.0f / KNB;
    uint2 o;
    *(__half2*)&o.x = __floats2half2_rn(a0 * s, a1 * s);
    *(__half2*)&o.y = __floats2half2_rn(a2 * s, a3 * s);
    *(uint2*)(dst + (size_t)n * 128 + lane * 4) = o;
}

__global__ void __launch_bounds__(256) k_gather0() {
    int t = blockIdx.x * blockDim.x + threadIdx.x;
    int n = t >> 5; if (n >= NPTS) return;
    int lane = t & 31;
    const int* kn = d_knn32 + n * KNB;
    float a0 = 0.f, a1 = 0.f, a2 = 0.f, a3 = 0.f;
#pragma unroll
    for (int k = 0; k < KNB; k++) {
        uint2 v = *(const uint2*)(d_G1f + (size_t)kn[k] * 128 + lane * 4);
        __half2 p0 = *(__half2*)&v.x, p1 = *(__half2*)&v.y;
        a0 += __low2float(p0); a1 += __high2float(p0);
        a2 += __low2float(p1); a3 += __high2float(p1);
    }
    const float s = 1.0f / KNB;
    size_t o = (size_t)n * 384 + 256 + lane * 4;
    *(__half2*)(d_Gcf + o)     = __floats2half2_rn(a0 * s, a1 * s);
    *(__half2*)(d_Gcf + o + 2) = __floats2half2_rn(a2 * s, a3 * s);
}

__global__ void __launch_bounds__(256) k_gather1() {
    int t = blockIdx.x * blockDim.x + threadIdx.x;
    int n = t >> 5; if (n >= NPTS) return;
    gather128_f16(d_x1f, d_ax1f, n, t & 31);
}

__global__ void __launch_bounds__(256) k_gather2() {
    int t = blockIdx.x * blockDim.x + threadIdx.x;
    int n = t >> 5; if (n >= NPTS) return;
    gather128_f16(d_ax1f, d_aaxf, n, t & 31);
}

// ================= fp16 tensor-core GEMM cores (HMMA + ldmatrix) =================
__device__ __forceinline__ void mma16816(float* c, const unsigned* a, unsigned b0, unsigned b1) {
    asm volatile(
        "mma.sync.aligned.m16n8k16.row.col.f32.f16.f16.f32 "
        "{%0,%1,%2,%3}, {%4,%5,%6,%7}, {%8,%9}, {%0,%1,%2,%3};"
        : "+f"(c[0]), "+f"(c[1]), "+f"(c[2]), "+f"(c[3])
        : "r"(a[0]), "r"(a[1]), "r"(a[2]), "r"(a[3]), "r"(b0), "r"(b1));
}

#define LDMX4(d, addr) \
    asm volatile("ldmatrix.sync.aligned.m8n8.x4.shared.b16 {%0,%1,%2,%3}, [%4];" \
        : "=r"((d)[0]), "=r"((d)[1]), "=r"((d)[2]), "=r"((d)[3]) : "r"(addr))

__device__ __forceinline__ void cp16(__half* s, const __half* g) {
    unsigned sa = (unsigned)__cvta_generic_to_shared(s);
    asm volatile("cp.async.cg.shared.global [%0], [%1], 16;" :: "r"(sa), "l"(g));
}

#define PLANE (128 * ASTR)
#define GEMM_SMEM2  (2 * 3 * PLANE * 2)   // dual-plane core: 61440 B
#define GEMM_SMEM1  (2 * 2 * PLANE * 2)   // single-plane core: 40960 B

#define LANE_OFFS() \
    const int a_off = (warp_m * 32 + ((lane >> 3) & 1) * 8 + (lane & 7)) * ASTR \
                      + ((lane >> 4) * 8); \
    const int b_off = (warp_n * 64 + ((lane >> 4) & 1) * 8 + (lane & 7)) * ASTR \
                      + (((lane >> 3) & 1) * 8);

// -------- dual-plane core: C = A*Bh + A*Bl --------
__device__ __forceinline__ void ld_stage2(__half* s,
        const __half* A, int lda, const __half* Bh, const __half* Bl, int ldb,
        int k0, int tid) {
#pragma unroll
    for (int i = 0; i < 2; i++) {
        int chunk = tid + i * 256;
        int r = chunk >> 2, c8 = (chunk & 3) * 8;
        cp16(s + 0 * PLANE + r * ASTR + c8, A  + (size_t)r * lda + k0 + c8);
        cp16(s + 1 * PLANE + r * ASTR + c8, Bh + (size_t)r * ldb + k0 + c8);
        cp16(s + 2 * PLANE + r * ASTR + c8, Bl + (size_t)r * ldb + k0 + c8);
    }
}

__device__ __forceinline__ void gemm_mma2(
        const __half* __restrict__ A, int lda,
        const __half* __restrict__ Bh, const __half* __restrict__ Bl, int ldb,
        int K, float (&acc)[2][8][4]) {
    extern __shared__ __half smdyn[];
    const int tid = threadIdx.x;
    const int lane = tid & 31, wid = tid >> 5;
    const int warp_m = wid & 3, warp_n = wid >> 2;
    const int nk = K / 32;
    const unsigned smbase = (unsigned)__cvta_generic_to_shared(smdyn);
    LANE_OFFS();

    ld_stage2(smdyn, A, lda, Bh, Bl, ldb, 0, tid);
    asm volatile("cp.async.commit_group;");
    for (int t = 0; t < nk; t++) {
        int st = t & 1;
        if (t + 1 < nk) {
            ld_stage2(smdyn + (st ^ 1) * 3 * PLANE, A, lda, Bh, Bl, ldb, (t + 1) * 32, tid);
            asm volatile("cp.async.commit_group;");
            asm volatile("cp.async.wait_group 1;");
        } else {
            asm volatile("cp.async.wait_group 0;");
        }
        __syncthreads();
        const unsigned aB  = smbase + (st * 3 * PLANE) * 2;
        const unsigned bhB = aB + PLANE * 2;
        const unsigned blB = aB + 2 * PLANE * 2;
#pragma unroll
        for (int ks = 0; ks < 32; ks += 16) {
            unsigned af[2][4];
            LDMX4(af[0], aB + (unsigned)(a_off + ks) * 2);
            LDMX4(af[1], aB + (unsigned)(a_off + 16 * ASTR + ks) * 2);
#pragma unroll
            for (int p = 0; p < 4; p++) {
                unsigned bh[4], bl[4];
                unsigned bo = (unsigned)(b_off + p * 16 * ASTR + ks) * 2;
                LDMX4(bh, bhB + bo);
                LDMX4(bl, blB + bo);
                mma16816(acc[0][2 * p],     af[0], bh[0], bh[1]);
                mma16816(acc[1][2 * p],     af[1], bh[0], bh[1]);
                mma16816(acc[0][2 * p],     af[0], bl[0], bl[1]);
                mma16816(acc[1][2 * p],     af[1], bl[0], bl[1]);
                mma16816(acc[0][2 * p + 1], af[0], bh[2], bh[3]);
                mma16816(acc[1][2 * p + 1], af[1], bh[2], bh[3]);
                mma16816(acc[0][2 * p + 1], af[0], bl[2], bl[3]);
                mma16816(acc[1][2 * p + 1], af[1], bl[2], bl[3]);
            }
        }
        __syncthreads();
    }
}

// -------- single-plane core: C = A*Bh --------
__device__ __forceinline__ void ld_stage1(__half* s,
        const __half* A, int lda, const __half* Bh, int ldb, int k0, int tid) {
#pragma unroll
    for (int i = 0; i < 2; i++) {
        int chunk = tid + i * 256;
        int r = chunk >> 2, c8 = (chunk & 3) * 8;
        cp16(s + 0 * PLANE + r * ASTR + c8, A  + (size_t)r * lda + k0 + c8);
        cp16(s + 1 * PLANE + r * ASTR + c8, Bh + (size_t)r * ldb + k0 + c8);
    }
}

__device__ __forceinline__ void gemm_mma1(
        const __half* __restrict__ A, int lda,
        const __half* __restrict__ Bh, int ldb,
        int K, float (&acc)[2][8][4]) {
    extern __shared__ __half smdyn[];
    const int tid = threadIdx.x;
    const int lane = tid & 31, wid = tid >> 5;
    const int warp_m = wid & 3, warp_n = wid >> 2;
    const int nk = K / 32;
    const unsigned smbase = (unsigned)__cvta_generic_to_shared(smdyn);
    LANE_OFFS();

    ld_stage1(smdyn, A, lda, Bh, ldb, 0, tid);
    asm volatile("cp.async.commit_group;");
    for (int t = 0; t < nk; t++) {
        int st = t & 1;
        if (t + 1 < nk) {
            ld_stage1(smdyn + (st ^ 1) * 2 * PLANE, A, lda, Bh, ldb, (t + 1) * 32, tid);
            asm volatile("cp.async.commit_group;");
            asm volatile("cp.async.wait_group 1;");
        } else {
            asm volatile("cp.async.wait_group 0;");
        }
        __syncthreads();
        const unsigned aB  = smbase + (st * 2 * PLANE) * 2;
        const unsigned bhB = aB + PLANE * 2;
#pragma unroll
        for (int ks = 0; ks < 32; ks += 16) {
            unsigned af[2][4];
            LDMX4(af[0], aB + (unsigned)(a_off + ks) * 2);
            LDMX4(af[1], aB + (unsigned)(a_off + 16 * ASTR + ks) * 2);
#pragma unroll
            for (int p = 0; p < 4; p++) {
                unsigned bh[4];
                unsigned bo = (unsigned)(b_off + p * 16 * ASTR + ks) * 2;
                LDMX4(bh, bhB + bo);
                mma16816(acc[0][2 * p],     af[0], bh[0], bh[1]);
                mma16816(acc[1][2 * p],     af[1], bh[0], bh[1]);
                mma16816(acc[0][2 * p + 1], af[0], bh[2], bh[3]);
                mma16816(acc[1][2 * p + 1], af[1], bh[2], bh[3]);
            }
        }
        __syncthreads();
    }
}

#define EPILOG_COORDS() \
    const int lane = threadIdx.x & 31, wid = threadIdx.x >> 5; \
    const int warp_m = wid & 3, warp_n = wid >> 2; \
    const int grp4 = lane >> 2, tig = lane & 3;

// ---------------- GEMM C0: Gcat @ W2[:, :384]^T + bsum ; fa = C0 + dv (+ fp16 plane) ----------------
__global__ void __launch_bounds__(256, 2) k_gemmC0() {
    float acc[2][8][4] = {};
    gemm_mma2(d_Gcf + (size_t)blockIdx.x * 128 * 384, 384,
              d_w2h + (size_t)blockIdx.y * 128 * 512, d_w2l + (size_t)blockIdx.y * 128 * 512, 512,
              384, acc);
    EPILOG_COORDS();
#pragma unroll
    for (int mi = 0; mi < 2; mi++) {
#pragma unroll
        for (int ni = 0; ni < 8; ni++) {
            int r0 = blockIdx.x * 128 + warp_m * 32 + mi * 16 + grp4;
            int cc = blockIdx.y * 128 + warp_n * 64 + ni * 8 + tig * 2;
            float2 bs = *(const float2*)(d_bsum + cc);
            float2 dv = *(const float2*)(d_dv + cc);
            float* a = acc[mi][ni];
#pragma unroll
            for (int h2 = 0; h2 < 2; h2++) {
                int r = r0 + h2 * 8;
                size_t o = (size_t)r * 512 + cc;
                float c0 = a[2 * h2 + 0] + bs.x, c1 = a[2 * h2 + 1] + bs.y;
                *(float2*)(d_C0 + o) = make_float2(c0, c1);
                float f0 = c0 + dv.x, f1 = c1 + dv.y;
                *(float2*)(d_fa + o) = make_float2(f0, f1);
                *(__half2*)(d_faf + o) = __floats2half2_rn(f0, f1);
            }
        }
    }
}

// ---------------- GEMM1a: x1 = f @ w_mlp1^T + b  (N=128, dual-plane) ----------------
__global__ void __launch_bounds__(256, 2) k_gemm1a(int fsel, const float* __restrict__ b_mlp1) {
    const __half* Af = (fsel ? d_fbf : d_faf) + (size_t)blockIdx.x * 128 * 512;
    float acc[2][8][4] = {};
    gemm_mma2(Af, 512, d_wch, d_wcl, 512, 512, acc);
    EPILOG_COORDS();
#pragma unroll
    for (int mi = 0; mi < 2; mi++) {
#pragma unroll
        for (int ni = 0; ni < 8; ni++) {
            int r0 = blockIdx.x * 128 + warp_m * 32 + mi * 16 + grp4;
            int cl = warp_n * 64 + ni * 8 + tig * 2;
            float2 bs = *(const float2*)(b_mlp1 + cl);
            float* a = acc[mi][ni];
#pragma unroll
            for (int h2 = 0; h2 < 2; h2++) {
                int r = r0 + h2 * 8;
                *(__half2*)(d_x1f + (size_t)r * 128 + cl) =
                    __floats2half2_rn(a[2 * h2 + 0] + bs.x, a[2 * h2 + 1] + bs.y);
            }
        }
    }
}

// ---------------- GEMM1b: r = f @ w_res^T  (N=512, single-plane fp16 weights) ----------------
__global__ void __launch_bounds__(256, 2) k_gemm1b(int fsel) {
    const __half* Af = (fsel ? d_fbf : d_faf) + (size_t)blockIdx.x * 128 * 512;
    const __half* Bh = d_wch + (size_t)(blockIdx.y + 1) * 128 * 512;   // w_res rows
    float acc[2][8][4] = {};
    gemm_mma1(Af, 512, Bh, 512, 512, acc);
    EPILOG_COORDS();
#pragma unroll
    for (int mi = 0; mi < 2; mi++) {
#pragma unroll
        for (int ni = 0; ni < 8; ni++) {
            int r0 = blockIdx.x * 128 + warp_m * 32 + mi * 16 + grp4;
            int cc = blockIdx.y * 128 + warp_n * 64 + ni * 8 + tig * 2;
            float* a = acc[mi][ni];
#pragma unroll
            for (int h2 = 0; h2 < 2; h2++) {
                int r = r0 + h2 * 8;
                *(float2*)(d_r + (size_t)r * 512 + cc) =
                    make_float2(a[2 * h2 + 0], a[2 * h2 + 1]);
            }
        }
    }
}

// ---------------- GEMM2: f_new = C0 + f + r + aax1 @ W2[:,384:512]^T  (K=128) ----------------
__global__ void __launch_bounds__(256, 2) k_gemm2(int fsel, int dsel, float* __restrict__ outp) {
    const float* f = fsel ? d_fb : d_fa;
    float* dst = (dsel == 0) ? d_fb : (dsel == 1) ? d_fa : outp;
    __half* dstf = (dsel == 0) ? d_fbf : d_faf;
    float acc[2][8][4] = {};
    gemm_mma2(d_aaxf + (size_t)blockIdx.x * 128 * 128, 128,
              d_w2h + (size_t)blockIdx.y * 128 * 512 + 384,
              d_w2l + (size_t)blockIdx.y * 128 * 512 + 384, 512,
              128, acc);
    EPILOG_COORDS();
#pragma unroll
    for (int mi = 0; mi < 2; mi++) {
#pragma unroll
        for (int ni = 0; ni < 8; ni++) {
            int r0 = blockIdx.x * 128 + warp_m * 32 + mi * 16 + grp4;
            int cc = blockIdx.y * 128 + warp_n * 64 + ni * 8 + tig * 2;
            float* a = acc[mi][ni];
#pragma unroll
            for (int h2 = 0; h2 < 2; h2++) {
                int r = r0 + h2 * 8;
                size_t o = (size_t)r * 512 + cc;
                float2 c0 = *(const float2*)(d_C0 + o);
                float2 fv = *(const float2*)(f + o);
                float2 rv = *(const float2*)(d_r + o);
                float v0 = a[2 * h2 + 0] + c0.x + fv.x + rv.x;
                float v1 = a[2 * h2 + 1] + c0.y + fv.y + rv.y;
                *(float2*)(dst + o) = make_float2(v0, v1);
                if (dsel != 2)
                    *(__half2*)(dstf + o) = __floats2half2_rn(v0, v1);
            }
        }
    }
}

// ---------------- launch ----------------
extern "C" void kernel_launch(void* const* d_in, const int* in_sizes, int n_in,
                              void* d_out, int out_size) {
    const float* inputs = (const float*)d_in[0];
    const void*  knn    = d_in[1];
    const float* w_mlp1 = (const float*)d_in[2];
    const float* b_mlp1 = (const float*)d_in[3];
    const float* w_lfa1 = (const float*)d_in[4];
    const float* b_lfa1 = (const float*)d_in[5];
    const float* w_lfa2 = (const float*)d_in[6];
    const float* b_lfa2 = (const float*)d_in[7];
    const float* w_mlp2 = (const float*)d_in[8];
    const float* b_mlp2 = (const float*)d_in[9];
    const float* w_res  = (const float*)d_in[10];
    const float* b_res  = (const float*)d_in[11];
    float* out = (float*)d_out;

    static int smem_set = 0;
    if (!smem_set) {
        cudaFuncSetAttribute(k_gemmC0, cudaFuncAttributeMaxDynamicSharedMemorySize, GEMM_SMEM2);
        cudaFuncSetAttribute(k_gemm1a, cudaFuncAttributeMaxDynamicSharedMemorySize, GEMM_SMEM2);
        cudaFuncSetAttribute(k_gemm1b, cudaFuncAttributeMaxDynamicSharedMemorySize, GEMM_SMEM1);
        cudaFuncSetAttribute(k_gemm2,  cudaFuncAttributeMaxDynamicSharedMemorySize, GEMM_SMEM2);
        smem_set = 1;
    }

    k_detect<<<128, 256>>>(knn);
    k_cvt<<<(NPTS * KNB) / 256, 256>>>(knn);
    k_wcvt<<<(640 * 512) / 256, 256>>>(w_mlp2, w_mlp1, w_res);
    k_prep<<<NPTS / 256, 256>>>(inputs);
    k_smallg<<<257, 256>>>(w_lfa1, b_lfa1, w_lfa2, b_lfa2,
                           w_mlp2, b_mlp1, b_mlp2, b_res);
    k_gather0<<<(NPTS * 32) / 256, 256>>>();
    dim3 gC0(128, 4);
    k_gemmC0<<<gC0, 256, GEMM_SMEM2>>>();

    int fsel = 0;
    for (int it = 0; it < 3; it++) {
        k_gemm1a<<<dim3(128, 1), 256, GEMM_SMEM2>>>(fsel, b_mlp1);
        k_gemm1b<<<dim3(128, 4), 256, GEMM_SMEM1>>>(fsel);
        k_gather1<<<(NPTS * 32) / 256, 256>>>();
        k_gather2<<<(NPTS * 32) / 256, 256>>>();
        int dsel = (it == 2) ? 2 : (fsel == 0 ? 0 : 1);
        k_gemm2<<<dim3(128, 4), 256, GEMM_SMEM2>>>(fsel, dsel, out);
        fsel ^= 1;
    }
    (void)in_sizes; (void)n_in; (void)out_size;
}

// round 13
// speedup vs baseline: 1.6101x; 1.0511x over previous
#include <cuda_runtime.h>
#include <cuda_fp16.h>
#include <math.h>
#include <stdint.h>

#define NPTS 16384
#define KNB  16
#define ASTR 40   // smem row stride (halfs): 32 + 8 pad, conflict-free, 80B (16B aligned)

// ---------------- device scratch (static: no allocations allowed) ----------------
__device__ float d_geo[NPTS * 4];
__device__ int   d_knn32[NPTS * KNB];
__device__ int   d_knn_bad;                  // 0 => int64 knn, nonzero => int32
__device__ float d_C0[(size_t)NPTS * 512];
__device__ float d_fa[(size_t)NPTS * 512];
__device__ float d_fb[(size_t)NPTS * 512];
__device__ float d_r[(size_t)NPTS * 512];    // f @ w_res^T
__device__ float d_dv[512];
__device__ float d_bsum[512];

// fp16 planes
__device__ __half d_G1f[NPTS * 128];
__device__ __half d_x1f[NPTS * 128];
__device__ __half d_ax1f[NPTS * 128];
__device__ __half d_Gcf[(size_t)NPTS * 384];
__device__ __half d_faf[(size_t)NPTS * 512];
__device__ __half d_fbf[(size_t)NPTS * 512];
__device__ __half d_aaxf[NPTS * 128];
__device__ __half d_w2h[512 * 512], d_w2l[512 * 512];
__device__ __half d_wch[640 * 512];                 // [w_mlp1 ; w_res] hi
__device__ __half d_wcl[128 * 512];                 // w_mlp1 lo only

__device__ __forceinline__ void cvt_hl(float x, __half& h, __half& l) {
    h = __float2half_rn(x);
    l = __float2half_rn(x - __half2float(h));
}

// ---------------- knn dtype detection + convert ----------------
__global__ void k_detect(const void* __restrict__ knn) {
    const long long* p = (const long long*)knn;
    const int total = NPTS * KNB / 2;
    int local = 0;
    for (int i = blockIdx.x * blockDim.x + threadIdx.x; i < total; i += gridDim.x * blockDim.x) {
        long long v = p[i];
        if (v < 0 || v >= NPTS) local = 1;
    }
    if (local) atomicOr(&d_knn_bad, 1);
}

__global__ void k_cvt(const void* __restrict__ knn) {
    int i = blockIdx.x * blockDim.x + threadIdx.x;
    if (i >= NPTS * KNB) return;
    if (d_knn_bad)
        d_knn32[i] = ((const int*)knn)[i];
    else
        d_knn32[i] = (int)((const long long*)knn)[i];
}

// ---------------- weight planes ----------------
__global__ void k_wcvt(const float* __restrict__ w_mlp2, const float* __restrict__ w_mlp1,
                       const float* __restrict__ w_res) {
    int i = blockIdx.x * blockDim.x + threadIdx.x;
    if (i >= 640 * 512) return;
    __half h, l;
    if (i < 512 * 512) {
        cvt_hl(w_mlp2[i], h, l);
        d_w2h[i] = h; d_w2l[i] = l;
    }
    float v = (i < 128 * 512) ? w_mlp1[i] : w_res[i - 128 * 512];
    cvt_hl(v, h, l);
    d_wch[i] = h;
    if (i < 128 * 512) d_wcl[i] = l;
}

// ---------------- prep: geo mean ----------------
__global__ void k_prep(const float* __restrict__ inp) {
    int n = blockIdx.x * blockDim.x + threadIdx.x;
    if (n >= NPTS) return;
    float xi = inp[3 * n + 0], yi = inp[3 * n + 1], zi = inp[3 * n + 2];
    float sx = 0.f, sy = 0.f, sz = 0.f, sn = 0.f;
#pragma unroll
    for (int k = 0; k < KNB; k++) {
        int j = d_knn32[n * KNB + k];
        float dx = xi - inp[3 * j + 0];
        float dy = yi - inp[3 * j + 1];
        float dz = zi - inp[3 * j + 2];
        sx += dx; sy += dy; sz += dz;
        sn += sqrtf(dx * dx + dy * dy + dz * dz);
    }
    const float s = 1.0f / KNB;
    d_geo[n * 4 + 0] = sx * s;
    d_geo[n * 4 + 1] = sy * s;
    d_geo[n * 4 + 2] = sz * s;
    d_geo[n * 4 + 3] = sn * s;
}

// ---------------- tiny geo linears + vec tail ----------------
__global__ void __launch_bounds__(256) k_smallg(
        const float* __restrict__ w_lfa1, const float* __restrict__ b_lfa1,
        const float* __restrict__ w_lfa2, const float* __restrict__ b_lfa2,
        const float* __restrict__ w_mlp2, const float* __restrict__ b_mlp1,
        const float* __restrict__ b_mlp2, const float* __restrict__ b_res) {
    int tid = threadIdx.x;
    if (blockIdx.x == 256) {
        int j = tid * 2;
        if (j < 512) {
#pragma unroll
            for (int t = 0; t < 2; t++) {
                int jj = j + t;
                d_bsum[jj] = b_mlp2[jj] + b_res[jj];
                float s = 0.f;
#pragma unroll 8
                for (int c = 0; c < 128; c++) s += w_mlp2[jj * 512 + 384 + c] * b_mlp1[c];
                d_dv[jj] = s;
            }
        }
        return;
    }
    __shared__ float s_w2[256 * 4], s_b2[256], s_w1[128 * 4], s_b1[128];
    for (int i = tid; i < 1024; i += 256) s_w2[i] = w_lfa2[i];
    for (int i = tid; i < 512;  i += 256) s_w1[i] = w_lfa1[i];
    for (int i = tid; i < 256;  i += 256) s_b2[i] = b_lfa2[i];
    if (tid < 128) s_b1[tid] = b_lfa1[tid];
    __syncthreads();
    int wid = tid >> 5, lane = tid & 31;
#pragma unroll 1
    for (int p = 0; p < 8; p++) {
        int n = (blockIdx.x * 8 + wid) * 8 + p;
        float4 g = *(const float4*)(d_geo + n * 4);
#pragma unroll
        for (int t = 0; t < 2; t++) {
            int j0 = t * 128 + lane * 4;
            float r[4];
#pragma unroll
            for (int u = 0; u < 4; u++) {
                int j = j0 + u;
                r[u] = s_b2[j] + g.x * s_w2[j * 4 + 0] + g.y * s_w2[j * 4 + 1]
                               + g.z * s_w2[j * 4 + 2] + g.w * s_w2[j * 4 + 3];
            }
            size_t o = (size_t)n * 384 + j0;
            *(__half2*)(d_Gcf + o)     = __floats2half2_rn(r[0], r[1]);
            *(__half2*)(d_Gcf + o + 2) = __floats2half2_rn(r[2], r[3]);
        }
        {
            int j0 = lane * 4;
            float r[4];
#pragma unroll
            for (int u = 0; u < 4; u++) {
                int j = j0 + u;
                r[u] = s_b1[j] + g.x * s_w1[j * 4 + 0] + g.y * s_w1[j * 4 + 1]
                               + g.z * s_w1[j * 4 + 2] + g.w * s_w1[j * 4 + 3];
            }
            size_t o = (size_t)n * 128 + j0;
            *(__half2*)(d_G1f + o)     = __floats2half2_rn(r[0], r[1]);
            *(__half2*)(d_G1f + o + 2) = __floats2half2_rn(r[2], r[3]);
        }
    }
}

// ---------------- gather-mean kernels (one warp per point, fp16 rows) ----------------
__device__ __forceinline__ void gather128_f16(const __half* __restrict__ src,
                                              __half* __restrict__ dst,
                                              int n, int lane) {
    const int* kn = d_knn32 + n * KNB;
    float a0 = 0.f, a1 = 0.f, a2 = 0.f, a3 = 0.f;
#pragma unroll
    for (int k = 0; k < KNB; k++) {
        uint2 v = *(const uint2*)(src + (size_t)kn[k] * 128 + lane * 4);
        __half2 p0 = *(__half2*)&v.x, p1 = *(__half2*)&v.y;
        a0 += __low2float(p0); a1 += __high2float(p0);
        a2 += __low2float(p1); a3 += __high2float(p1);
    }
    const float s = 1.0f / KNB;
    uint2 o;
    *(__half2*)&o.x = __floats2half2_rn(a0 * s, a1 * s);
    *(__half2*)&o.y = __floats2half2_rn(a2 * s, a3 * s);
    *(uint2*)(dst + (size_t)n * 128 + lane * 4) = o;
}

__global__ void __launch_bounds__(256) k_gather0() {
    int t = blockIdx.x * blockDim.x + threadIdx.x;
    int n = t >> 5; if (n >= NPTS) return;
    int lane = t & 31;
    const int* kn = d_knn32 + n * KNB;
    float a0 = 0.f, a1 = 0.f, a2 = 0.f, a3 = 0.f;
#pragma unroll
    for (int k = 0; k < KNB; k++) {
        uint2 v = *(const uint2*)(d_G1f + (size_t)kn[k] * 128 + lane * 4);
        __half2 p0 = *(__half2*)&v.x, p1 = *(__half2*)&v.y;
        a0 += __low2float(p0); a1 += __high2float(p0);
        a2 += __low2float(p1); a3 += __high2float(p1);
    }
    const float s = 1.0f / KNB;
    size_t o = (size_t)n * 384 + 256 + lane * 4;
    *(__half2*)(d_Gcf + o)     = __floats2half2_rn(a0 * s, a1 * s);
    *(__half2*)(d_Gcf + o + 2) = __floats2half2_rn(a2 * s, a3 * s);
}

__global__ void __launch_bounds__(256) k_gather1() {
    int t = blockIdx.x * blockDim.x + threadIdx.x;
    int n = t >> 5; if (n >= NPTS) return;
    gather128_f16(d_x1f, d_ax1f, n, t & 31);
}

__global__ void __launch_bounds__(256) k_gather2() {
    int t = blockIdx.x * blockDim.x + threadIdx.x;
    int n = t >> 5; if (n >= NPTS) return;
    gather128_f16(d_ax1f, d_aaxf, n, t & 31);
}

// ================= fp16 tensor-core GEMM cores (HMMA + ldmatrix) =================
__device__ __forceinline__ void mma16816(float* c, const unsigned* a, unsigned b0, unsigned b1) {
    asm volatile(
        "mma.sync.aligned.m16n8k16.row.col.f32.f16.f16.f32 "
        "{%0,%1,%2,%3}, {%4,%5,%6,%7}, {%8,%9}, {%0,%1,%2,%3};"
        : "+f"(c[0]), "+f"(c[1]), "+f"(c[2]), "+f"(c[3])
        : "r"(a[0]), "r"(a[1]), "r"(a[2]), "r"(a[3]), "r"(b0), "r"(b1));
}

#define LDMX4(d, addr) \
    asm volatile("ldmatrix.sync.aligned.m8n8.x4.shared.b16 {%0,%1,%2,%3}, [%4];" \
        : "=r"((d)[0]), "=r"((d)[1]), "=r"((d)[2]), "=r"((d)[3]) : "r"(addr))

__device__ __forceinline__ void cp16(__half* s, const __half* g) {
    unsigned sa = (unsigned)__cvta_generic_to_shared(s);
    asm volatile("cp.async.cg.shared.global [%0], [%1], 16;" :: "r"(sa), "l"(g));
}

#define PLANE (128 * ASTR)
#define GEMM_SMEM2  (2 * 3 * PLANE * 2)   // dual-plane core: 61440 B
#define GEMM_SMEM1  (2 * 2 * PLANE * 2)   // single-plane core: 40960 B

#define LANE_OFFS() \
    const int a_off = (warp_m * 32 + ((lane >> 3) & 1) * 8 + (lane & 7)) * ASTR \
                      + ((lane >> 4) * 8); \
    const int b_off = (warp_n * 64 + ((lane >> 4) & 1) * 8 + (lane & 7)) * ASTR \
                      + (((lane >> 3) & 1) * 8);

// -------- dual-plane core: C = A*Bh + A*Bl --------
__device__ __forceinline__ void ld_stage2(__half* s,
        const __half* A, int lda, const __half* Bh, const __half* Bl, int ldb,
        int k0, int tid) {
#pragma unroll
    for (int i = 0; i < 2; i++) {
        int chunk = tid + i * 256;
        int r = chunk >> 2, c8 = (chunk & 3) * 8;
        cp16(s + 0 * PLANE + r * ASTR + c8, A  + (size_t)r * lda + k0 + c8);
        cp16(s + 1 * PLANE + r * ASTR + c8, Bh + (size_t)r * ldb + k0 + c8);
        cp16(s + 2 * PLANE + r * ASTR + c8, Bl + (size_t)r * ldb + k0 + c8);
    }
}

__device__ __forceinline__ void gemm_mma2(
        const __half* __restrict__ A, int lda,
        const __half* __restrict__ Bh, const __half* __restrict__ Bl, int ldb,
        int K, float (&acc)[2][8][4]) {
    extern __shared__ __half smdyn[];
    const int tid = threadIdx.x;
    const int lane = tid & 31, wid = tid >> 5;
    const int warp_m = wid & 3, warp_n = wid >> 2;
    const int nk = K / 32;
    const unsigned smbase = (unsigned)__cvta_generic_to_shared(smdyn);
    LANE_OFFS();

    ld_stage2(smdyn, A, lda, Bh, Bl, ldb, 0, tid);
    asm volatile("cp.async.commit_group;");
    for (int t = 0; t < nk; t++) {
        int st = t & 1;
        if (t + 1 < nk) {
            ld_stage2(smdyn + (st ^ 1) * 3 * PLANE, A, lda, Bh, Bl, ldb, (t + 1) * 32, tid);
            asm volatile("cp.async.commit_group;");
            asm volatile("cp.async.wait_group 1;");
        } else {
            asm volatile("cp.async.wait_group 0;");
        }
        __syncthreads();
        const unsigned aB  = smbase + (st * 3 * PLANE) * 2;
        const unsigned bhB = aB + PLANE * 2;
        const unsigned blB = aB + 2 * PLANE * 2;
#pragma unroll
        for (int ks = 0; ks < 32; ks += 16) {
            unsigned af[2][4];
            LDMX4(af[0], aB + (unsigned)(a_off + ks) * 2);
            LDMX4(af[1], aB + (unsigned)(a_off + 16 * ASTR + ks) * 2);
#pragma unroll
            for (int p = 0; p < 4; p++) {
                unsigned bh[4], bl[4];
                unsigned bo = (unsigned)(b_off + p * 16 * ASTR + ks) * 2;
                LDMX4(bh, bhB + bo);
                LDMX4(bl, blB + bo);
                mma16816(acc[0][2 * p],     af[0], bh[0], bh[1]);
                mma16816(acc[1][2 * p],     af[1], bh[0], bh[1]);
                mma16816(acc[0][2 * p],     af[0], bl[0], bl[1]);
                mma16816(acc[1][2 * p],     af[1], bl[0], bl[1]);
                mma16816(acc[0][2 * p + 1], af[0], bh[2], bh[3]);
                mma16816(acc[1][2 * p + 1], af[1], bh[2], bh[3]);
                mma16816(acc[0][2 * p + 1], af[0], bl[2], bl[3]);
                mma16816(acc[1][2 * p + 1], af[1], bl[2], bl[3]);
            }
        }
        __syncthreads();
    }
}

// -------- single-plane core: C = A*Bh --------
__device__ __forceinline__ void ld_stage1(__half* s,
        const __half* A, int lda, const __half* Bh, int ldb, int k0, int tid) {
#pragma unroll
    for (int i = 0; i < 2; i++) {
        int chunk = tid + i * 256;
        int r = chunk >> 2, c8 = (chunk & 3) * 8;
        cp16(s + 0 * PLANE + r * ASTR + c8, A  + (size_t)r * lda + k0 + c8);
        cp16(s + 1 * PLANE + r * ASTR + c8, Bh + (size_t)r * ldb + k0 + c8);
    }
}

__device__ __forceinline__ void gemm_mma1(
        const __half* __restrict__ A, int lda,
        const __half* __restrict__ Bh, int ldb,
        int K, float (&acc)[2][8][4]) {
    extern __shared__ __half smdyn[];
    const int tid = threadIdx.x;
    const int lane = tid & 31, wid = tid >> 5;
    const int warp_m = wid & 3, warp_n = wid >> 2;
    const int nk = K / 32;
    const unsigned smbase = (unsigned)__cvta_generic_to_shared(smdyn);
    LANE_OFFS();

    ld_stage1(smdyn, A, lda, Bh, ldb, 0, tid);
    asm volatile("cp.async.commit_group;");
    for (int t = 0; t < nk; t++) {
        int st = t & 1;
        if (t + 1 < nk) {
            ld_stage1(smdyn + (st ^ 1) * 2 * PLANE, A, lda, Bh, ldb, (t + 1) * 32, tid);
            asm volatile("cp.async.commit_group;");
            asm volatile("cp.async.wait_group 1;");
        } else {
            asm volatile("cp.async.wait_group 0;");
        }
        __syncthreads();
        const unsigned aB  = smbase + (st * 2 * PLANE) * 2;
        const unsigned bhB = aB + PLANE * 2;
#pragma unroll
        for (int ks = 0; ks < 32; ks += 16) {
            unsigned af[2][4];
            LDMX4(af[0], aB + (unsigned)(a_off + ks) * 2);
            LDMX4(af[1], aB + (unsigned)(a_off + 16 * ASTR + ks) * 2);
#pragma unroll
            for (int p = 0; p < 4; p++) {
                unsigned bh[4];
                unsigned bo = (unsigned)(b_off + p * 16 * ASTR + ks) * 2;
                LDMX4(bh, bhB + bo);
                mma16816(acc[0][2 * p],     af[0], bh[0], bh[1]);
                mma16816(acc[1][2 * p],     af[1], bh[0], bh[1]);
                mma16816(acc[0][2 * p + 1], af[0], bh[2], bh[3]);
                mma16816(acc[1][2 * p + 1], af[1], bh[2], bh[3]);
            }
        }
        __syncthreads();
    }
}

#define EPILOG_COORDS() \
    const int lane = threadIdx.x & 31, wid = threadIdx.x >> 5; \
    const int warp_m = wid & 3, warp_n = wid >> 2; \
    const int grp4 = lane >> 2, tig = lane & 3;

// ---------------- GEMM C0: Gcat @ W2[:, :384]^T + bsum ; fa = C0 + dv (+ fp16 plane) ----------------
__global__ void __launch_bounds__(256, 2) k_gemmC0() {
    float acc[2][8][4] = {};
    gemm_mma2(d_Gcf + (size_t)blockIdx.x * 128 * 384, 384,
              d_w2h + (size_t)blockIdx.y * 128 * 512, d_w2l + (size_t)blockIdx.y * 128 * 512, 512,
              384, acc);
    EPILOG_COORDS();
#pragma unroll
    for (int mi = 0; mi < 2; mi++) {
#pragma unroll
        for (int ni = 0; ni < 8; ni++) {
            int r0 = blockIdx.x * 128 + warp_m * 32 + mi * 16 + grp4;
            int cc = blockIdx.y * 128 + warp_n * 64 + ni * 8 + tig * 2;
            float2 bs = *(const float2*)(d_bsum + cc);
            float2 dv = *(const float2*)(d_dv + cc);
            float* a = acc[mi][ni];
#pragma unroll
            for (int h2 = 0; h2 < 2; h2++) {
                int r = r0 + h2 * 8;
                size_t o = (size_t)r * 512 + cc;
                float c0 = a[2 * h2 + 0] + bs.x, c1 = a[2 * h2 + 1] + bs.y;
                *(float2*)(d_C0 + o) = make_float2(c0, c1);
                float f0 = c0 + dv.x, f1 = c1 + dv.y;
                *(float2*)(d_fa + o) = make_float2(f0, f1);
                *(__half2*)(d_faf + o) = __floats2half2_rn(f0, f1);
            }
        }
    }
}

// ---------------- GEMM1a: x1 = f @ w_mlp1^T + b  (N=128, dual-plane) ----------------
__global__ void __launch_bounds__(256, 2) k_gemm1a(int fsel, const float* __restrict__ b_mlp1) {
    const __half* Af = (fsel ? d_fbf : d_faf) + (size_t)blockIdx.x * 128 * 512;
    float acc[2][8][4] = {};
    gemm_mma2(Af, 512, d_wch, d_wcl, 512, 512, acc);
    EPILOG_COORDS();
#pragma unroll
    for (int mi = 0; mi < 2; mi++) {
#pragma unroll
        for (int ni = 0; ni < 8; ni++) {
            int r0 = blockIdx.x * 128 + warp_m * 32 + mi * 16 + grp4;
            int cl = warp_n * 64 + ni * 8 + tig * 2;
            float2 bs = *(const float2*)(b_mlp1 + cl);
            float* a = acc[mi][ni];
#pragma unroll
            for (int h2 = 0; h2 < 2; h2++) {
                int r = r0 + h2 * 8;
                *(__half2*)(d_x1f + (size_t)r * 128 + cl) =
                    __floats2half2_rn(a[2 * h2 + 0] + bs.x, a[2 * h2 + 1] + bs.y);
            }
        }
    }
}

// ---------------- GEMM1b: r = f @ w_res^T  (N=512, single-plane fp16 weights) ----------------
__global__ void __launch_bounds__(256, 2) k_gemm1b(int fsel) {
    const __half* Af = (fsel ? d_fbf : d_faf) + (size_t)blockIdx.x * 128 * 512;
    const __half* Bh = d_wch + (size_t)(blockIdx.y + 1) * 128 * 512;   // w_res rows
    float acc[2][8][4] = {};
    gemm_mma1(Af, 512, Bh, 512, 512, acc);
    EPILOG_COORDS();
#pragma unroll
    for (int mi = 0; mi < 2; mi++) {
#pragma unroll
        for (int ni = 0; ni < 8; ni++) {
            int r0 = blockIdx.x * 128 + warp_m * 32 + mi * 16 + grp4;
            int cc = blockIdx.y * 128 + warp_n * 64 + ni * 8 + tig * 2;
            float* a = acc[mi][ni];
#pragma unroll
            for (int h2 = 0; h2 < 2; h2++) {
                int r = r0 + h2 * 8;
                *(float2*)(d_r + (size_t)r * 512 + cc) =
                    make_float2(a[2 * h2 + 0], a[2 * h2 + 1]);
            }
        }
    }
}

// ---------------- GEMM2: f_new = C0 + f + r + aax1 @ W2[:,384:512]^T (single-plane, K=128) ----------------
__global__ void __launch_bounds__(256, 2) k_gemm2(int fsel, int dsel, float* __restrict__ outp) {
    const float* f = fsel ? d_fb : d_fa;
    float* dst = (dsel == 0) ? d_fb : (dsel == 1) ? d_fa : outp;
    __half* dstf = (dsel == 0) ? d_fbf : d_faf;
    float acc[2][8][4] = {};
    gemm_mma1(d_aaxf + (size_t)blockIdx.x * 128 * 128, 128,
              d_w2h + (size_t)blockIdx.y * 128 * 512 + 384, 512,
              128, acc);
    EPILOG_COORDS();
#pragma unroll
    for (int mi = 0; mi < 2; mi++) {
#pragma unroll
        for (int ni = 0; ni < 8; ni++) {
            int r0 = blockIdx.x * 128 + warp_m * 32 + mi * 16 + grp4;
            int cc = blockIdx.y * 128 + warp_n * 64 + ni * 8 + tig * 2;
            float* a = acc[mi][ni];
#pragma unroll
            for (int h2 = 0; h2 < 2; h2++) {
                int r = r0 + h2 * 8;
                size_t o = (size_t)r * 512 + cc;
                float2 c0 = *(const float2*)(d_C0 + o);
                float2 fv = *(const float2*)(f + o);
                float2 rv = *(const float2*)(d_r + o);
                float v0 = a[2 * h2 + 0] + c0.x + fv.x + rv.x;
                float v1 = a[2 * h2 + 1] + c0.y + fv.y + rv.y;
                *(float2*)(dst + o) = make_float2(v0, v1);
                if (dsel != 2)
                    *(__half2*)(dstf + o) = __floats2half2_rn(v0, v1);
            }
        }
    }
}

// ---------------- launch ----------------
extern "C" void kernel_launch(void* const* d_in, const int* in_sizes, int n_in,
                              void* d_out, int out_size) {
    const float* inputs = (const float*)d_in[0];
    const void*  knn    = d_in[1];
    const float* w_mlp1 = (const float*)d_in[2];
    const float* b_mlp1 = (const float*)d_in[3];
    const float* w_lfa1 = (const float*)d_in[4];
    const float* b_lfa1 = (const float*)d_in[5];
    const float* w_lfa2 = (const float*)d_in[6];
    const float* b_lfa2 = (const float*)d_in[7];
    const float* w_mlp2 = (const float*)d_in[8];
    const float* b_mlp2 = (const float*)d_in[9];
    const float* w_res  = (const float*)d_in[10];
    const float* b_res  = (const float*)d_in[11];
    float* out = (float*)d_out;

    static int init_done = 0;
    static cudaStream_t s1;
    static cudaEvent_t ev_fork, ev_join;
    if (!init_done) {
        cudaFuncSetAttribute(k_gemmC0, cudaFuncAttributeMaxDynamicSharedMemorySize, GEMM_SMEM2);
        cudaFuncSetAttribute(k_gemm1a, cudaFuncAttributeMaxDynamicSharedMemorySize, GEMM_SMEM2);
        cudaFuncSetAttribute(k_gemm1b, cudaFuncAttributeMaxDynamicSharedMemorySize, GEMM_SMEM1);
        cudaFuncSetAttribute(k_gemm2,  cudaFuncAttributeMaxDynamicSharedMemorySize, GEMM_SMEM1);
        cudaStreamCreateWithFlags(&s1, cudaStreamNonBlocking);
        cudaEventCreateWithFlags(&ev_fork, cudaEventDisableTiming);
        cudaEventCreateWithFlags(&ev_join, cudaEventDisableTiming);
        init_done = 1;
    }

    // ---- prologue: weight conversion overlapped with knn/geo chain ----
    cudaEventRecord(ev_fork, 0);
    cudaStreamWaitEvent(s1, ev_fork, 0);
    k_wcvt<<<(640 * 512) / 256, 256, 0, s1>>>(w_mlp2, w_mlp1, w_res);
    cudaEventRecord(ev_join, s1);

    k_detect<<<128, 256>>>(knn);
    k_cvt<<<(NPTS * KNB) / 256, 256>>>(knn);
    k_prep<<<NPTS / 256, 256>>>(inputs);
    k_smallg<<<257, 256>>>(w_lfa1, b_lfa1, w_lfa2, b_lfa2,
                           w_mlp2, b_mlp1, b_mlp2, b_res);
    k_gather0<<<(NPTS * 32) / 256, 256>>>();
    cudaStreamWaitEvent(0, ev_join, 0);
    k_gemmC0<<<dim3(128, 4), 256, GEMM_SMEM2>>>();

    int fsel = 0;
    for (int it = 0; it < 3; it++) {
        // fork: gemm1b (needs only f) runs beside gemm1a -> gather1 -> gather2
        cudaEventRecord(ev_fork, 0);
        cudaStreamWaitEvent(s1, ev_fork, 0);
        k_gemm1b<<<dim3(128, 4), 256, GEMM_SMEM1, s1>>>(fsel);
        cudaEventRecord(ev_join, s1);

        k_gemm1a<<<dim3(128, 1), 256, GEMM_SMEM2>>>(fsel, b_mlp1);
        k_gather1<<<(NPTS * 32) / 256, 256>>>();
        k_gather2<<<(NPTS * 32) / 256, 256>>>();

        cudaStreamWaitEvent(0, ev_join, 0);
        int dsel = (it == 2) ? 2 : (fsel == 0 ? 0 : 1);
        k_gemm2<<<dim3(128, 4), 256, GEMM_SMEM1>>>(fsel, dsel, out);
        fsel ^= 1;
    }
    (void)in_sizes; (void)n_in; (void)out_size;
}

// round 14
// speedup vs baseline: 1.7881x; 1.1105x over previous
#include <cuda_runtime.h>
#include <cuda_fp16.h>
#include <math.h>
#include <stdint.h>

#define NPTS 16384
#define KNB  16
#define ASTR 40   // smem row stride (halfs): 32 + 8 pad, conflict-free, 80B (16B aligned)

// ---------------- device scratch (static: no allocations allowed) ----------------
__device__ float d_geo[NPTS * 4];
__device__ int   d_knn32[NPTS * KNB];
__device__ int   d_knn_bad;                  // 0 => int64 knn, nonzero => int32
__device__ float d_C0[(size_t)NPTS * 512];
__device__ float d_fa[(size_t)NPTS * 512];
__device__ float d_fb[(size_t)NPTS * 512];
__device__ float d_r[(size_t)NPTS * 512];    // f @ w_res^T
__device__ float d_dv[512];
__device__ float d_bsum[512];

// fp16 planes (activations single-plane; ALL weights single-plane hi)
__device__ __half d_G1f[NPTS * 128];
__device__ __half d_x1f[NPTS * 128];
__device__ __half d_ax1f[NPTS * 128];
__device__ __half d_Gcf[(size_t)NPTS * 384];
__device__ __half d_faf[(size_t)NPTS * 512];
__device__ __half d_fbf[(size_t)NPTS * 512];
__device__ __half d_aaxf[NPTS * 128];
__device__ __half d_w2h[512 * 512];
__device__ __half d_wch[640 * 512];                 // [w_mlp1 ; w_res] hi

// ---------------- knn dtype detection + convert ----------------
__global__ void k_detect(const void* __restrict__ knn) {
    const long long* p = (const long long*)knn;
    const int total = NPTS * KNB / 2;
    int local = 0;
    for (int i = blockIdx.x * blockDim.x + threadIdx.x; i < total; i += gridDim.x * blockDim.x) {
        long long v = p[i];
        if (v < 0 || v >= NPTS) local = 1;
    }
    if (local) atomicOr(&d_knn_bad, 1);
}

__global__ void k_cvt(const void* __restrict__ knn) {
    int i = blockIdx.x * blockDim.x + threadIdx.x;
    if (i >= NPTS * KNB) return;
    if (d_knn_bad)
        d_knn32[i] = ((const int*)knn)[i];
    else
        d_knn32[i] = (int)((const long long*)knn)[i];
}

// ---------------- weight planes (hi only) ----------------
__global__ void k_wcvt(const float* __restrict__ w_mlp2, const float* __restrict__ w_mlp1,
                       const float* __restrict__ w_res) {
    int i = blockIdx.x * blockDim.x + threadIdx.x;
    if (i >= 640 * 512) return;
    if (i < 512 * 512) d_w2h[i] = __float2half_rn(w_mlp2[i]);
    float v = (i < 128 * 512) ? w_mlp1[i] : w_res[i - 128 * 512];
    d_wch[i] = __float2half_rn(v);
}

// ---------------- prep: geo mean ----------------
__global__ void k_prep(const float* __restrict__ inp) {
    int n = blockIdx.x * blockDim.x + threadIdx.x;
    if (n >= NPTS) return;
    float xi = inp[3 * n + 0], yi = inp[3 * n + 1], zi = inp[3 * n + 2];
    float sx = 0.f, sy = 0.f, sz = 0.f, sn = 0.f;
#pragma unroll
    for (int k = 0; k < KNB; k++) {
        int j = d_knn32[n * KNB + k];
        float dx = xi - inp[3 * j + 0];
        float dy = yi - inp[3 * j + 1];
        float dz = zi - inp[3 * j + 2];
        sx += dx; sy += dy; sz += dz;
        sn += sqrtf(dx * dx + dy * dy + dz * dz);
    }
    const float s = 1.0f / KNB;
    d_geo[n * 4 + 0] = sx * s;
    d_geo[n * 4 + 1] = sy * s;
    d_geo[n * 4 + 2] = sz * s;
    d_geo[n * 4 + 3] = sn * s;
}

// ---------------- tiny geo linears + vec tail ----------------
__global__ void __launch_bounds__(256) k_smallg(
        const float* __restrict__ w_lfa1, const float* __restrict__ b_lfa1,
        const float* __restrict__ w_lfa2, const float* __restrict__ b_lfa2,
        const float* __restrict__ w_mlp2, const float* __restrict__ b_mlp1,
        const float* __restrict__ b_mlp2, const float* __restrict__ b_res) {
    int tid = threadIdx.x;
    if (blockIdx.x == 256) {
        int j = tid * 2;
        if (j < 512) {
#pragma unroll
            for (int t = 0; t < 2; t++) {
                int jj = j + t;
                d_bsum[jj] = b_mlp2[jj] + b_res[jj];
                float s = 0.f;
#pragma unroll 8
                for (int c = 0; c < 128; c++) s += w_mlp2[jj * 512 + 384 + c] * b_mlp1[c];
                d_dv[jj] = s;
            }
        }
        return;
    }
    __shared__ float s_w2[256 * 4], s_b2[256], s_w1[128 * 4], s_b1[128];
    for (int i = tid; i < 1024; i += 256) s_w2[i] = w_lfa2[i];
    for (int i = tid; i < 512;  i += 256) s_w1[i] = w_lfa1[i];
    for (int i = tid; i < 256;  i += 256) s_b2[i] = b_lfa2[i];
    if (tid < 128) s_b1[tid] = b_lfa1[tid];
    __syncthreads();
    int wid = tid >> 5, lane = tid & 31;
#pragma unroll 1
    for (int p = 0; p < 8; p++) {
        int n = (blockIdx.x * 8 + wid) * 8 + p;
        float4 g = *(const float4*)(d_geo + n * 4);
#pragma unroll
        for (int t = 0; t < 2; t++) {
            int j0 = t * 128 + lane * 4;
            float r[4];
#pragma unroll
            for (int u = 0; u < 4; u++) {
                int j = j0 + u;
                r[u] = s_b2[j] + g.x * s_w2[j * 4 + 0] + g.y * s_w2[j * 4 + 1]
                               + g.z * s_w2[j * 4 + 2] + g.w * s_w2[j * 4 + 3];
            }
            size_t o = (size_t)n * 384 + j0;
            *(__half2*)(d_Gcf + o)     = __floats2half2_rn(r[0], r[1]);
            *(__half2*)(d_Gcf + o + 2) = __floats2half2_rn(r[2], r[3]);
        }
        {
            int j0 = lane * 4;
            float r[4];
#pragma unroll
            for (int u = 0; u < 4; u++) {
                int j = j0 + u;
                r[u] = s_b1[j] + g.x * s_w1[j * 4 + 0] + g.y * s_w1[j * 4 + 1]
                               + g.z * s_w1[j * 4 + 2] + g.w * s_w1[j * 4 + 3];
            }
            size_t o = (size_t)n * 128 + j0;
            *(__half2*)(d_G1f + o)     = __floats2half2_rn(r[0], r[1]);
            *(__half2*)(d_G1f + o + 2) = __floats2half2_rn(r[2], r[3]);
        }
    }
}

// ---------------- gather-mean kernels (one warp per point, fp16 rows) ----------------
__device__ __forceinline__ void gather128_f16(const __half* __restrict__ src,
                                              __half* __restrict__ dst,
                                              int n, int lane) {
    const int* kn = d_knn32 + n * KNB;
    float a0 = 0.f, a1 = 0.f, a2 = 0.f, a3 = 0.f;
#pragma unroll
    for (int k = 0; k < KNB; k++) {
        uint2 v = *(const uint2*)(src + (size_t)kn[k] * 128 + lane * 4);
        __half2 p0 = *(__half2*)&v.x, p1 = *(__half2*)&v.y;
        a0 += __low2float(p0); a1 += __high2float(p0);
        a2 += __low2float(p1); a3 += __high2float(p1);
    }
    const float s = 1.0f / KNB;
    uint2 o;
    *(__half2*)&o.x = __floats2half2_rn(a0 * s, a1 * s);
    *(__half2*)&o.y = __floats2half2_rn(a2 * s, a3 * s);
    *(uint2*)(dst + (size_t)n * 128 + lane * 4) = o;
}

__global__ void __launch_bounds__(256) k_gather0() {
    int t = blockIdx.x * blockDim.x + threadIdx.x;
    int n = t >> 5; if (n >= NPTS) return;
    int lane = t & 31;
    const int* kn = d_knn32 + n * KNB;
    float a0 = 0.f, a1 = 0.f, a2 = 0.f, a3 = 0.f;
#pragma unroll
    for (int k = 0; k < KNB; k++) {
        uint2 v = *(const uint2*)(d_G1f + (size_t)kn[k] * 128 + lane * 4);
        __half2 p0 = *(__half2*)&v.x, p1 = *(__half2*)&v.y;
        a0 += __low2float(p0); a1 += __high2float(p0);
        a2 += __low2float(p1); a3 += __high2float(p1);
    }
    const float s = 1.0f / KNB;
    size_t o = (size_t)n * 384 + 256 + lane * 4;
    *(__half2*)(d_Gcf + o)     = __floats2half2_rn(a0 * s, a1 * s);
    *(__half2*)(d_Gcf + o + 2) = __floats2half2_rn(a2 * s, a3 * s);
}

__global__ void __launch_bounds__(256) k_gather1() {
    int t = blockIdx.x * blockDim.x + threadIdx.x;
    int n = t >> 5; if (n >= NPTS) return;
    gather128_f16(d_x1f, d_ax1f, n, t & 31);
}

__global__ void __launch_bounds__(256) k_gather2() {
    int t = blockIdx.x * blockDim.x + threadIdx.x;
    int n = t >> 5; if (n >= NPTS) return;
    gather128_f16(d_ax1f, d_aaxf, n, t & 31);
}

// ================= fp16 tensor-core GEMM core (HMMA + ldmatrix, single-plane) =================
__device__ __forceinline__ void mma16816(float* c, const unsigned* a, unsigned b0, unsigned b1) {
    asm volatile(
        "mma.sync.aligned.m16n8k16.row.col.f32.f16.f16.f32 "
        "{%0,%1,%2,%3}, {%4,%5,%6,%7}, {%8,%9}, {%0,%1,%2,%3};"
        : "+f"(c[0]), "+f"(c[1]), "+f"(c[2]), "+f"(c[3])
        : "r"(a[0]), "r"(a[1]), "r"(a[2]), "r"(a[3]), "r"(b0), "r"(b1));
}

#define LDMX4(d, addr) \
    asm volatile("ldmatrix.sync.aligned.m8n8.x4.shared.b16 {%0,%1,%2,%3}, [%4];" \
        : "=r"((d)[0]), "=r"((d)[1]), "=r"((d)[2]), "=r"((d)[3]) : "r"(addr))

__device__ __forceinline__ void cp16(__half* s, const __half* g) {
    unsigned sa = (unsigned)__cvta_generic_to_shared(s);
    asm volatile("cp.async.cg.shared.global [%0], [%1], 16;" :: "r"(sa), "l"(g));
}

#define PLANE (128 * ASTR)
#define GEMM_SMEM1  (2 * 2 * PLANE * 2)   // 2 stages x 2 planes: 40960 B

#define LANE_OFFS() \
    const int a_off = (warp_m * 32 + ((lane >> 3) & 1) * 8 + (lane & 7)) * ASTR \
                      + ((lane >> 4) * 8); \
    const int b_off = (warp_n * 64 + ((lane >> 4) & 1) * 8 + (lane & 7)) * ASTR \
                      + (((lane >> 3) & 1) * 8);

__device__ __forceinline__ void ld_stage1(__half* s,
        const __half* A, int lda, const __half* Bh, int ldb, int k0, int tid) {
#pragma unroll
    for (int i = 0; i < 2; i++) {
        int chunk = tid + i * 256;
        int r = chunk >> 2, c8 = (chunk & 3) * 8;
        cp16(s + 0 * PLANE + r * ASTR + c8, A  + (size_t)r * lda + k0 + c8);
        cp16(s + 1 * PLANE + r * ASTR + c8, Bh + (size_t)r * ldb + k0 + c8);
    }
}

__device__ __forceinline__ void gemm_mma1(
        const __half* __restrict__ A, int lda,
        const __half* __restrict__ Bh, int ldb,
        int K, float (&acc)[2][8][4]) {
    extern __shared__ __half smdyn[];
    const int tid = threadIdx.x;
    const int lane = tid & 31, wid = tid >> 5;
    const int warp_m = wid & 3, warp_n = wid >> 2;
    const int nk = K / 32;
    const unsigned smbase = (unsigned)__cvta_generic_to_shared(smdyn);
    LANE_OFFS();

    ld_stage1(smdyn, A, lda, Bh, ldb, 0, tid);
    asm volatile("cp.async.commit_group;");
    for (int t = 0; t < nk; t++) {
        int st = t & 1;
        if (t + 1 < nk) {
            ld_stage1(smdyn + (st ^ 1) * 2 * PLANE, A, lda, Bh, ldb, (t + 1) * 32, tid);
            asm volatile("cp.async.commit_group;");
            asm volatile("cp.async.wait_group 1;");
        } else {
            asm volatile("cp.async.wait_group 0;");
        }
        __syncthreads();
        const unsigned aB  = smbase + (st * 2 * PLANE) * 2;
        const unsigned bhB = aB + PLANE * 2;
#pragma unroll
        for (int ks = 0; ks < 32; ks += 16) {
            unsigned af[2][4];
            LDMX4(af[0], aB + (unsigned)(a_off + ks) * 2);
            LDMX4(af[1], aB + (unsigned)(a_off + 16 * ASTR + ks) * 2);
#pragma unroll
            for (int p = 0; p < 4; p++) {
                unsigned bh[4];
                unsigned bo = (unsigned)(b_off + p * 16 * ASTR + ks) * 2;
                LDMX4(bh, bhB + bo);
                mma16816(acc[0][2 * p],     af[0], bh[0], bh[1]);
                mma16816(acc[1][2 * p],     af[1], bh[0], bh[1]);
                mma16816(acc[0][2 * p + 1], af[0], bh[2], bh[3]);
                mma16816(acc[1][2 * p + 1], af[1], bh[2], bh[3]);
            }
        }
        __syncthreads();
    }
}

#define EPILOG_COORDS() \
    const int lane = threadIdx.x & 31, wid = threadIdx.x >> 5; \
    const int warp_m = wid & 3, warp_n = wid >> 2; \
    const int grp4 = lane >> 2, tig = lane & 3;

// ---------------- GEMM C0: Gcat @ W2[:, :384]^T + bsum ; fa = C0 + dv (+ fp16 plane) ----------------
__global__ void __launch_bounds__(256, 2) k_gemmC0() {
    float acc[2][8][4] = {};
    gemm_mma1(d_Gcf + (size_t)blockIdx.x * 128 * 384, 384,
              d_w2h + (size_t)blockIdx.y * 128 * 512, 512, 384, acc);
    EPILOG_COORDS();
#pragma unroll
    for (int mi = 0; mi < 2; mi++) {
#pragma unroll
        for (int ni = 0; ni < 8; ni++) {
            int r0 = blockIdx.x * 128 + warp_m * 32 + mi * 16 + grp4;
            int cc = blockIdx.y * 128 + warp_n * 64 + ni * 8 + tig * 2;
            float2 bs = *(const float2*)(d_bsum + cc);
            float2 dv = *(const float2*)(d_dv + cc);
            float* a = acc[mi][ni];
#pragma unroll
            for (int h2 = 0; h2 < 2; h2++) {
                int r = r0 + h2 * 8;
                size_t o = (size_t)r * 512 + cc;
                float c0 = a[2 * h2 + 0] + bs.x, c1 = a[2 * h2 + 1] + bs.y;
                *(float2*)(d_C0 + o) = make_float2(c0, c1);
                float f0 = c0 + dv.x, f1 = c1 + dv.y;
                *(float2*)(d_fa + o) = make_float2(f0, f1);
                *(__half2*)(d_faf + o) = __floats2half2_rn(f0, f1);
            }
        }
    }
}

// ---------------- GEMM1a: x1 = f @ w_mlp1^T + b  (N=128, single-plane) ----------------
__global__ void __launch_bounds__(256, 2) k_gemm1a(int fsel, const float* __restrict__ b_mlp1) {
    const __half* Af = (fsel ? d_fbf : d_faf) + (size_t)blockIdx.x * 128 * 512;
    float acc[2][8][4] = {};
    gemm_mma1(Af, 512, d_wch, 512, 512, acc);
    EPILOG_COORDS();
#pragma unroll
    for (int mi = 0; mi < 2; mi++) {
#pragma unroll
        for (int ni = 0; ni < 8; ni++) {
            int r0 = blockIdx.x * 128 + warp_m * 32 + mi * 16 + grp4;
            int cl = warp_n * 64 + ni * 8 + tig * 2;
            float2 bs = *(const float2*)(b_mlp1 + cl);
            float* a = acc[mi][ni];
#pragma unroll
            for (int h2 = 0; h2 < 2; h2++) {
                int r = r0 + h2 * 8;
                *(__half2*)(d_x1f + (size_t)r * 128 + cl) =
                    __floats2half2_rn(a[2 * h2 + 0] + bs.x, a[2 * h2 + 1] + bs.y);
            }
        }
    }
}

// ---------------- GEMM1b: r = f @ w_res^T  (N=512, single-plane) ----------------
__global__ void __launch_bounds__(256, 2) k_gemm1b(int fsel) {
    const __half* Af = (fsel ? d_fbf : d_faf) + (size_t)blockIdx.x * 128 * 512;
    const __half* Bh = d_wch + (size_t)(blockIdx.y + 1) * 128 * 512;   // w_res rows
    float acc[2][8][4] = {};
    gemm_mma1(Af, 512, Bh, 512, 512, acc);
    EPILOG_COORDS();
#pragma unroll
    for (int mi = 0; mi < 2; mi++) {
#pragma unroll
        for (int ni = 0; ni < 8; ni++) {
            int r0 = blockIdx.x * 128 + warp_m * 32 + mi * 16 + grp4;
            int cc = blockIdx.y * 128 + warp_n * 64 + ni * 8 + tig * 2;
            float* a = acc[mi][ni];
#pragma unroll
            for (int h2 = 0; h2 < 2; h2++) {
                int r = r0 + h2 * 8;
                *(float2*)(d_r + (size_t)r * 512 + cc) =
                    make_float2(a[2 * h2 + 0], a[2 * h2 + 1]);
            }
        }
    }
}

// ---------------- GEMM2: f_new = C0 + f + r + aax1 @ W2[:,384:512]^T (single-plane, K=128) ----------------
__global__ void __launch_bounds__(256, 2) k_gemm2(int fsel, int dsel, float* __restrict__ outp) {
    const float* f = fsel ? d_fb : d_fa;
    float* dst = (dsel == 0) ? d_fb : (dsel == 1) ? d_fa : outp;
    __half* dstf = (dsel == 0) ? d_fbf : d_faf;
    float acc[2][8][4] = {};
    gemm_mma1(d_aaxf + (size_t)blockIdx.x * 128 * 128, 128,
              d_w2h + (size_t)blockIdx.y * 128 * 512 + 384, 512,
              128, acc);
    EPILOG_COORDS();
#pragma unroll
    for (int mi = 0; mi < 2; mi++) {
#pragma unroll
        for (int ni = 0; ni < 8; ni++) {
            int r0 = blockIdx.x * 128 + warp_m * 32 + mi * 16 + grp4;
            int cc = blockIdx.y * 128 + warp_n * 64 + ni * 8 + tig * 2;
            float* a = acc[mi][ni];
#pragma unroll
            for (int h2 = 0; h2 < 2; h2++) {
                int r = r0 + h2 * 8;
                size_t o = (size_t)r * 512 + cc;
                float2 c0 = *(const float2*)(d_C0 + o);
                float2 fv = *(const float2*)(f + o);
                float2 rv = *(const float2*)(d_r + o);
                float v0 = a[2 * h2 + 0] + c0.x + fv.x + rv.x;
                float v1 = a[2 * h2 + 1] + c0.y + fv.y + rv.y;
                *(float2*)(dst + o) = make_float2(v0, v1);
                if (dsel != 2)
                    *(__half2*)(dstf + o) = __floats2half2_rn(v0, v1);
            }
        }
    }
}

// ---------------- launch ----------------
extern "C" void kernel_launch(void* const* d_in, const int* in_sizes, int n_in,
                              void* d_out, int out_size) {
    const float* inputs = (const float*)d_in[0];
    const void*  knn    = d_in[1];
    const float* w_mlp1 = (const float*)d_in[2];
    const float* b_mlp1 = (const float*)d_in[3];
    const float* w_lfa1 = (const float*)d_in[4];
    const float* b_lfa1 = (const float*)d_in[5];
    const float* w_lfa2 = (const float*)d_in[6];
    const float* b_lfa2 = (const float*)d_in[7];
    const float* w_mlp2 = (const float*)d_in[8];
    const float* b_mlp2 = (const float*)d_in[9];
    const float* w_res  = (const float*)d_in[10];
    const float* b_res  = (const float*)d_in[11];
    float* out = (float*)d_out;

    static int init_done = 0;
    static cudaStream_t s1;
    static cudaEvent_t ev_fork, ev_join;
    if (!init_done) {
        cudaFuncSetAttribute(k_gemmC0, cudaFuncAttributeMaxDynamicSharedMemorySize, GEMM_SMEM1);
        cudaFuncSetAttribute(k_gemm1a, cudaFuncAttributeMaxDynamicSharedMemorySize, GEMM_SMEM1);
        cudaFuncSetAttribute(k_gemm1b, cudaFuncAttributeMaxDynamicSharedMemorySize, GEMM_SMEM1);
        cudaFuncSetAttribute(k_gemm2,  cudaFuncAttributeMaxDynamicSharedMemorySize, GEMM_SMEM1);
        cudaStreamCreateWithFlags(&s1, cudaStreamNonBlocking);
        cudaEventCreateWithFlags(&ev_fork, cudaEventDisableTiming);
        cudaEventCreateWithFlags(&ev_join, cudaEventDisableTiming);
        init_done = 1;
    }

    // ---- prologue: weight conversion overlapped with knn/geo chain ----
    cudaEventRecord(ev_fork, 0);
    cudaStreamWaitEvent(s1, ev_fork, 0);
    k_wcvt<<<(640 * 512) / 256, 256, 0, s1>>>(w_mlp2, w_mlp1, w_res);
    cudaEventRecord(ev_join, s1);

    k_detect<<<128, 256>>>(knn);
    k_cvt<<<(NPTS * KNB) / 256, 256>>>(knn);
    k_prep<<<NPTS / 256, 256>>>(inputs);
    k_smallg<<<257, 256>>>(w_lfa1, b_lfa1, w_lfa2, b_lfa2,
                           w_mlp2, b_mlp1, b_mlp2, b_res);
    k_gather0<<<(NPTS * 32) / 256, 256>>>();
    cudaStreamWaitEvent(0, ev_join, 0);
    k_gemmC0<<<dim3(128, 4), 256, GEMM_SMEM1>>>();

    int fsel = 0;
    for (int it = 0; it < 3; it++) {
        // fork: gemm1b (needs only f) runs beside gemm1a -> gather1 -> gather2
        cudaEventRecord(ev_fork, 0);
        cudaStreamWaitEvent(s1, ev_fork, 0);
        k_gemm1b<<<dim3(128, 4), 256, GEMM_SMEM1, s1>>>(fsel);
        cudaEventRecord(ev_join, s1);

        k_gemm1a<<<dim3(128, 1), 256, GEMM_SMEM1>>>(fsel, b_mlp1);
        k_gather1<<<(NPTS * 32) / 256, 256>>>();
        k_gather2<<<(NPTS * 32) / 256, 256>>>();

        cudaStreamWaitEvent(0, ev_join, 0);
        int dsel = (it == 2) ? 2 : (fsel == 0 ? 0 : 1);
        k_gemm2<<<dim3(128, 4), 256, GEMM_SMEM1>>>(fsel, dsel, out);
        fsel ^= 1;
    }
    (void)in_sizes; (void)n_in; (void)out_size;
}